// round 3
// baseline (speedup 1.0000x reference)
#include <cuda_runtime.h>
#include <cstdint>

// ---------------------------------------------------------------------------
// TemporalAttention, B200 sm_100a
// Decomposition:
//   1. gn_stats + gn_apply  : GroupNorm, transpose to [token=t*1024+hw, C], tf32-round
//   2. prep_weights         : tf32-round Wq|Wk|Wv concat + Wproj into scratch
//   3. setup_bias           : qb = b_q + t_mid@Wq^T ;  kb[fi] = b_k + t_rest[fi]@Wk^T
//   4. gemm<0>              : QKV = XN @ Wcat^T  (16384 x 1536 x 512), tf32 mma.sync
//   5. attn_kernel          : 4-frame softmax attention per (token, head)
//   6. gemm<1>              : OUT = ATTN @ Wproj^T + b_proj + x  (transposed epilogue)
// ---------------------------------------------------------------------------

#define T_DIM   16
#define C_DIM   512
#define HW_DIM  1024
#define NTOK    16384      // T*H*W
#define NQKV    1536
#define NGRP    32
#define GN_EPS  1e-5f

// scratch (device globals: allocation-free per harness rules)
__device__ float g_xn  [NTOK * C_DIM];      // normalized, transposed, tf32-rounded
__device__ float g_qkv [NTOK * NQKV];       // Q | K | V per token
__device__ float g_attn[NTOK * C_DIM];      // attention output (tf32-rounded)
__device__ float g_wcat[NQKV * C_DIM];      // Wq;Wk;Wv rows, tf32-rounded
__device__ float g_wproj[C_DIM * C_DIM];    // Wproj, tf32-rounded
__device__ float g_mu[512];                 // per (t, group)
__device__ float g_rs[512];
__device__ float g_qb[C_DIM];               // b_q + t_mid @ Wq^T
__device__ float g_kb[4 * C_DIM];           // b_k + t_rest[fi] @ Wk^T

__device__ __forceinline__ float to_tf32(float x) {
    uint32_t y;                               // tf32 cvt needs .b32 destination
    asm("cvt.rna.tf32.f32 %0, %1;" : "=r"(y) : "f"(x));
    return __uint_as_float(y);
}

// ---------------------------------------------------------------------------
// GroupNorm statistics: one block per (t, group); the group's data is one
// contiguous span of 16*1024 floats.
// ---------------------------------------------------------------------------
__global__ void __launch_bounds__(256) gn_stats(const float* __restrict__ x) {
    int b = blockIdx.x;                       // t*32 + g
    const float* base = x + (size_t)b * 16384;
    float s = 0.f, s2 = 0.f;
    for (int i = threadIdx.x; i < 16384; i += 256) {
        float v = base[i];
        s += v; s2 += v * v;
    }
    // warp + block reduce
    for (int o = 16; o; o >>= 1) {
        s  += __shfl_xor_sync(0xffffffffu, s,  o);
        s2 += __shfl_xor_sync(0xffffffffu, s2, o);
    }
    __shared__ float rs[8], rs2[8];
    int wid = threadIdx.x >> 5;
    if ((threadIdx.x & 31) == 0) { rs[wid] = s; rs2[wid] = s2; }
    __syncthreads();
    if (threadIdx.x == 0) {
        float a = 0.f, a2 = 0.f;
        #pragma unroll
        for (int i = 0; i < 8; i++) { a += rs[i]; a2 += rs2[i]; }
        float mu  = a  * (1.f / 16384.f);
        float var = a2 * (1.f / 16384.f) - mu * mu;
        g_mu[b] = mu;
        g_rs[b] = rsqrtf(var + GN_EPS);
    }
}

// ---------------------------------------------------------------------------
// Apply GN + scale/bias, transpose [t, c, hw] -> [t*1024+hw, c], round to tf32
// ---------------------------------------------------------------------------
__global__ void __launch_bounds__(256) gn_apply(const float* __restrict__ x,
                                                const float* __restrict__ gs,
                                                const float* __restrict__ gb) {
    __shared__ float tile[32][33];
    int t   = blockIdx.z;
    int c0  = blockIdx.y * 32;
    int hw0 = blockIdx.x * 32;
    #pragma unroll
    for (int i = 0; i < 4; i++) {
        int c = c0 + threadIdx.y + i * 8;
        float v = x[((size_t)t * C_DIM + c) * HW_DIM + hw0 + threadIdx.x];
        int grp = c >> 4;
        v = (v - g_mu[t * NGRP + grp]) * g_rs[t * NGRP + grp] * gs[c] + gb[c];
        tile[threadIdx.y + i * 8][threadIdx.x] = to_tf32(v);
    }
    __syncthreads();
    #pragma unroll
    for (int i = 0; i < 4; i++) {
        int hw = hw0 + threadIdx.y + i * 8;
        g_xn[((size_t)t * HW_DIM + hw) * C_DIM + c0 + threadIdx.x] =
            tile[threadIdx.x][threadIdx.y + i * 8];
    }
}

// ---------------------------------------------------------------------------
// tf32-round weights into scratch, concatenating Wq|Wk|Wv
// ---------------------------------------------------------------------------
__global__ void __launch_bounds__(256) prep_weights(const float* __restrict__ w_q,
                                                    const float* __restrict__ w_k,
                                                    const float* __restrict__ w_v,
                                                    const float* __restrict__ w_proj) {
    int i = blockIdx.x * 256 + threadIdx.x;   // 0 .. 262143
    if (i < 262144) {
        g_wcat[i]          = to_tf32(w_q[i]);
        g_wcat[262144 + i] = to_tf32(w_k[i]);
        g_wcat[524288 + i] = to_tf32(w_v[i]);
        g_wproj[i]         = to_tf32(w_proj[i]);
    }
}

// ---------------------------------------------------------------------------
// qb[j] = b_q[j] + sum_c temb(0)[c]   * w_q[j,c]
// kb[fi][j] = b_k[j] + sum_c temb(off)[c] * w_k[j,c],  off in {-2,-1,1,2}
// (full fp32 precision; these are exact linear decompositions of the reference)
// ---------------------------------------------------------------------------
__global__ void __launch_bounds__(512) setup_bias(const float* __restrict__ w_q,
                                                  const float* __restrict__ b_q,
                                                  const float* __restrict__ w_k,
                                                  const float* __restrict__ b_k) {
    __shared__ float temb[5][512];
    int tid = threadIdx.x;
    for (int i = tid; i < 5 * 512; i += 512) {
        int f = i >> 9, c = i & 511;
        float ts = (float)(f - 2);
        float val;
        if (c < 256) {
            float fr = __expf(-9.210340371976184f * (float)c * (1.f / 256.f));
            val = cosf(ts * fr);
        } else {
            float fr = __expf(-9.210340371976184f * (float)(c - 256) * (1.f / 256.f));
            val = sinf(ts * fr);
        }
        temb[f][c] = val;
    }
    __syncthreads();
    int j = tid;
    {
        float acc = b_q[j];
        const float* wr = w_q + (size_t)j * 512;
        for (int c = 0; c < 512; c++) acc += temb[2][c] * wr[c];
        g_qb[j] = acc;
    }
    const int fmap[4] = {0, 1, 3, 4};
    #pragma unroll
    for (int fi = 0; fi < 4; fi++) {
        float acc = b_k[j];
        const float* tr = temb[fmap[fi]];
        const float* wr = w_k + (size_t)j * 512;
        for (int c = 0; c < 512; c++) acc += tr[c] * wr[c];
        g_kb[fi * 512 + j] = acc;
    }
}

// ---------------------------------------------------------------------------
// TF32 GEMM: C[M,N] = A[M,512] @ B[N,512]^T   (both K-contiguous)
// 128x128x16 tiles, cp.async double buffer, 8 warps (2x4), warp tile 64x32,
// mma.sync.m16n8k8.tf32.  Pitch-20 smem rows -> conflict-free quad loads.
// MODE 0: A=g_xn,   B=g_wcat,  N=1536, epilogue += {qb | 0 | b_v}
// MODE 1: A=g_attn, B=g_wproj, N=512,  epilogue writes out[t,c,hw] = v+b_proj+x
// ---------------------------------------------------------------------------
__device__ __forceinline__ void cpa16(uint32_t dst, const void* src) {
    asm volatile("cp.async.cg.shared.global [%0], [%1], 16;\n" :: "r"(dst), "l"(src));
}
__device__ __forceinline__ void mma_tf32(float* c, const uint32_t* a, const uint32_t* b) {
    asm volatile(
        "mma.sync.aligned.m16n8k8.row.col.f32.tf32.tf32.f32 "
        "{%0,%1,%2,%3}, {%4,%5,%6,%7}, {%8,%9}, {%0,%1,%2,%3};"
        : "+f"(c[0]), "+f"(c[1]), "+f"(c[2]), "+f"(c[3])
        : "r"(a[0]), "r"(a[1]), "r"(a[2]), "r"(a[3]), "r"(b[0]), "r"(b[1]));
}

template <int MODE>
__global__ void __launch_bounds__(256) gemm_kernel(const float* __restrict__ xres,
                                                   float* __restrict__ out,
                                                   const float* __restrict__ b_v,
                                                   const float* __restrict__ b_proj) {
    constexpr int LDS_ = 20;                 // smem row pitch (floats): conflict-free
    const float* A = (MODE == 0) ? g_xn   : g_attn;
    const float* B = (MODE == 0) ? g_wcat : g_wproj;

    __shared__ float As[2][128 * LDS_];
    __shared__ float Bs[2][128 * LDS_];

    int m0 = blockIdx.y * 128;
    int n0 = blockIdx.x * 128;
    int tid = threadIdx.x;
    int wid = tid >> 5, lane = tid & 31;
    int wm = (wid & 1) * 64, wn = (wid >> 1) * 32;
    int g = lane >> 2, tg = lane & 3;

    // cp.async mapping: each thread owns rows (tid>>2) and (tid>>2)+64, 16B col chunk
    int lrow = tid >> 2;
    int lcol = (tid & 3) * 4;                 // float offset within 16-float row
    const float* gA = A + ((size_t)(m0 + lrow)) * 512 + lcol;
    const float* gB = B + ((size_t)(n0 + lrow)) * 512 + lcol;
    uint32_t asb = (uint32_t)__cvta_generic_to_shared(As);
    uint32_t bsb = (uint32_t)__cvta_generic_to_shared(Bs);
    uint32_t sa0 = (uint32_t)((lrow * LDS_ + lcol) * 4);
    uint32_t sa1 = (uint32_t)(((lrow + 64) * LDS_ + lcol) * 4);
    const uint32_t bufB = 128 * LDS_ * 4;

    auto load_tile = [&](int kt, int buf) {
        const float* a = gA + kt * 16;
        const float* b = gB + kt * 16;
        cpa16(asb + buf * bufB + sa0, a);
        cpa16(asb + buf * bufB + sa1, a + 64 * 512);
        cpa16(bsb + buf * bufB + sa0, b);
        cpa16(bsb + buf * bufB + sa1, b + 64 * 512);
    };

    float acc[4][4][4];
    #pragma unroll
    for (int i = 0; i < 4; i++)
        #pragma unroll
        for (int j = 0; j < 4; j++)
            #pragma unroll
            for (int r = 0; r < 4; r++) acc[i][j][r] = 0.f;

    load_tile(0, 0);
    asm volatile("cp.async.commit_group;\n" ::);

    for (int kt = 0; kt < 32; ++kt) {
        if (kt < 31) {
            load_tile(kt + 1, (kt + 1) & 1);
            asm volatile("cp.async.commit_group;\n" ::);
            asm volatile("cp.async.wait_group 1;\n" ::);
        } else {
            asm volatile("cp.async.wait_group 0;\n" ::);
        }
        __syncthreads();

        const float* as = As[kt & 1];
        const float* bs = Bs[kt & 1];
        #pragma unroll
        for (int kk = 0; kk < 16; kk += 8) {
            uint32_t af[4][4], bf[4][2];
            #pragma unroll
            for (int im = 0; im < 4; im++) {
                int r = wm + im * 16 + g;
                af[im][0] = __float_as_uint(as[r * LDS_ + kk + tg]);
                af[im][1] = __float_as_uint(as[(r + 8) * LDS_ + kk + tg]);
                af[im][2] = __float_as_uint(as[r * LDS_ + kk + tg + 4]);
                af[im][3] = __float_as_uint(as[(r + 8) * LDS_ + kk + tg + 4]);
            }
            #pragma unroll
            for (int in = 0; in < 4; in++) {
                int nr = wn + in * 8 + g;
                bf[in][0] = __float_as_uint(bs[nr * LDS_ + kk + tg]);
                bf[in][1] = __float_as_uint(bs[nr * LDS_ + kk + tg + 4]);
            }
            #pragma unroll
            for (int im = 0; im < 4; im++)
                #pragma unroll
                for (int in = 0; in < 4; in++)
                    mma_tf32(acc[im][in], af[im], bf[in]);
        }
        __syncthreads();
    }

    // epilogue
    #pragma unroll
    for (int im = 0; im < 4; im++) {
        #pragma unroll
        for (int in = 0; in < 4; in++) {
            int r = m0 + wm + im * 16 + g;
            int c = n0 + wn + in * 8 + tg * 2;
            if (MODE == 0) {
                auto bias = [&](int cc) -> float {
                    return (cc < 512) ? g_qb[cc] : ((cc < 1024) ? 0.f : b_v[cc - 1024]);
                };
                float2 v0 = make_float2(acc[im][in][0] + bias(c),
                                        acc[im][in][1] + bias(c + 1));
                float2 v1 = make_float2(acc[im][in][2] + bias(c),
                                        acc[im][in][3] + bias(c + 1));
                *(float2*)&g_qkv[(size_t)r * NQKV + c] = v0;
                *(float2*)&g_qkv[(size_t)(r + 8) * NQKV + c] = v1;
            } else {
                #pragma unroll
                for (int dr = 0; dr < 2; dr++) {
                    int rr = r + dr * 8;
                    int tt = rr >> 10, hw = rr & 1023;
                    #pragma unroll
                    for (int dc = 0; dc < 2; dc++) {
                        int cc = c + dc;
                        size_t oi = ((size_t)tt * C_DIM + cc) * HW_DIM + hw;
                        out[oi] = acc[im][in][dr * 2 + dc] + b_proj[cc] + xres[oi];
                    }
                }
            }
        }
    }
}

// ---------------------------------------------------------------------------
// Attention: one warp per token; per head: 4-frame scores -> softmax -> mix V.
// k gets the per-frame-offset bias kb[fi]; v bias folded into GEMM epilogue
// (sum of softmax weights is 1, so + b_v commutes through the mix).
// ---------------------------------------------------------------------------
__global__ void __launch_bounds__(256) attn_kernel() {
    int wid = threadIdx.x >> 5, lane = threadIdx.x & 31;
    int token = blockIdx.x * 8 + wid;
    int t = token >> 10, hw = token & 1023;
    const int offs[4] = {-2, -1, 1, 2};
    int tok2[4];
    #pragma unroll
    for (int fi = 0; fi < 4; fi++) {
        int ts = t + offs[fi];
        ts = ts < 0 ? 0 : (ts > 15 ? 15 : ts);
        tok2[fi] = (ts << 10) | hw;
    }
    const float* Q = g_qkv + (size_t)token * NQKV;
    float* O = g_attn + (size_t)token * C_DIM;

    #pragma unroll
    for (int h = 0; h < 8; ++h) {
        int cb = h * 64;
        float q0 = Q[cb + lane], q1 = Q[cb + 32 + lane];
        float s[4];
        #pragma unroll
        for (int fi = 0; fi < 4; fi++) {
            const float* Krow = g_qkv + (size_t)tok2[fi] * NQKV + 512 + cb;
            const float* kb = g_kb + fi * 512 + cb;
            float k0 = Krow[lane] + kb[lane];
            float k1 = Krow[32 + lane] + kb[32 + lane];
            float p = q0 * k0 + q1 * k1;
            for (int o = 16; o; o >>= 1) p += __shfl_xor_sync(0xffffffffu, p, o);
            s[fi] = p * 0.125f;               // dh^-0.5, dh=64
        }
        float m = fmaxf(fmaxf(s[0], s[1]), fmaxf(s[2], s[3]));
        float e[4], sum = 0.f;
        #pragma unroll
        for (int fi = 0; fi < 4; fi++) { e[fi] = __expf(s[fi] - m); sum += e[fi]; }
        float inv = 1.f / sum;
        float a0 = 0.f, a1 = 0.f;
        #pragma unroll
        for (int fi = 0; fi < 4; fi++) {
            const float* V = g_qkv + (size_t)tok2[fi] * NQKV + 1024 + cb;
            float p = e[fi] * inv;
            a0 += p * V[lane];
            a1 += p * V[32 + lane];
        }
        O[cb + lane]      = to_tf32(a0);      // RNA-round: proj GEMM reads as tf32
        O[cb + 32 + lane] = to_tf32(a1);
    }
}

// ---------------------------------------------------------------------------
extern "C" void kernel_launch(void* const* d_in, const int* in_sizes, int n_in,
                              void* d_out, int out_size) {
    const float* x       = (const float*)d_in[0];
    const float* w_q     = (const float*)d_in[1];
    const float* b_q     = (const float*)d_in[2];
    const float* w_k     = (const float*)d_in[3];
    const float* b_k     = (const float*)d_in[4];
    const float* w_v     = (const float*)d_in[5];
    const float* b_v     = (const float*)d_in[6];
    const float* w_proj  = (const float*)d_in[7];
    const float* b_proj  = (const float*)d_in[8];
    const float* gn_s    = (const float*)d_in[9];
    const float* gn_b    = (const float*)d_in[10];
    float* out = (float*)d_out;

    prep_weights<<<1024, 256>>>(w_q, w_k, w_v, w_proj);
    setup_bias<<<1, 512>>>(w_q, b_q, w_k, b_k);
    gn_stats<<<512, 256>>>(x);
    gn_apply<<<dim3(32, 16, 16), dim3(32, 8)>>>(x, gn_s, gn_b);
    gemm_kernel<0><<<dim3(12, 128), 256>>>(nullptr, nullptr, b_v, nullptr);
    attn_kernel<<<2048, 256>>>();
    gemm_kernel<1><<<dim3(4, 128), 256>>>(x, out, nullptr, b_proj);
}

// round 5
// speedup vs baseline: 4.4630x; 4.4630x over previous
#include <cuda_runtime.h>
#include <cuda_fp16.h>
#include <cstdint>

// ---------------------------------------------------------------------------
// TemporalAttention, B200 (harness targets compute_100 -> no tcgen05).
// FP16 m16n8k16 mma.sync GEMM path (halves MMA+LDS count vs tf32 k8).
//   gn_stats/gn_apply : GroupNorm + transpose to [token, C], fp16 out
//   prep_weights      : fp16 Wq|Wk|Wv concat + Wproj
//   setup_bias        : qb = b_q + t_mid@Wq^T ; kb[fi] = b_k + t_rest[fi]@Wk^T
//   gemm_fp16<0>      : QKV = XN @ Wcat^T  (fp32 accum) + bias epilogue
//   attn_kernel       : 4-frame softmax attention (float2), fp16 out
//   gemm_fp16<1>      : OUT = ATTN @ Wproj^T + b_proj + x
// ---------------------------------------------------------------------------

#define T_DIM   16
#define C_DIM   512
#define HW_DIM  1024
#define NTOK    16384
#define NQKV    1536
#define NGRP    32
#define GN_EPS  1e-5f

__device__ __half g_xn  [NTOK * C_DIM];
__device__ float  g_qkv [NTOK * NQKV];
__device__ __half g_attn[NTOK * C_DIM];
__device__ __half g_wcat[NQKV * C_DIM];
__device__ __half g_wproj[C_DIM * C_DIM];
__device__ float  g_mu[512];
__device__ float  g_rs[512];
__device__ float  g_qb[C_DIM];
__device__ float  g_kb[4 * C_DIM];

// ---------------------------------------------------------------------------
__global__ void __launch_bounds__(256) gn_stats(const float* __restrict__ x) {
    int b = blockIdx.x;                       // t*32 + g
    const float* base = x + (size_t)b * 16384;
    float s = 0.f, s2 = 0.f;
    for (int i = threadIdx.x; i < 16384; i += 256) {
        float v = base[i];
        s += v; s2 += v * v;
    }
    for (int o = 16; o; o >>= 1) {
        s  += __shfl_xor_sync(0xffffffffu, s,  o);
        s2 += __shfl_xor_sync(0xffffffffu, s2, o);
    }
    __shared__ float rs[8], rs2[8];
    int wid = threadIdx.x >> 5;
    if ((threadIdx.x & 31) == 0) { rs[wid] = s; rs2[wid] = s2; }
    __syncthreads();
    if (threadIdx.x == 0) {
        float a = 0.f, a2 = 0.f;
        #pragma unroll
        for (int i = 0; i < 8; i++) { a += rs[i]; a2 += rs2[i]; }
        float mu  = a  * (1.f / 16384.f);
        float var = a2 * (1.f / 16384.f) - mu * mu;
        g_mu[b] = mu;
        g_rs[b] = rsqrtf(var + GN_EPS);
    }
}

// ---------------------------------------------------------------------------
// GN apply + transpose [t,c,hw] -> [token, c], fp16 output
// ---------------------------------------------------------------------------
__global__ void __launch_bounds__(256) gn_apply(const float* __restrict__ x,
                                                const float* __restrict__ gs,
                                                const float* __restrict__ gb) {
    __shared__ float tile[32][33];
    int t   = blockIdx.z;
    int c0  = blockIdx.y * 32;
    int hw0 = blockIdx.x * 32;
    #pragma unroll
    for (int i = 0; i < 4; i++) {
        int c = c0 + threadIdx.y + i * 8;
        float v = x[((size_t)t * C_DIM + c) * HW_DIM + hw0 + threadIdx.x];
        int grp = c >> 4;
        v = (v - g_mu[t * NGRP + grp]) * g_rs[t * NGRP + grp] * gs[c] + gb[c];
        tile[threadIdx.y + i * 8][threadIdx.x] = v;
    }
    __syncthreads();
    #pragma unroll
    for (int i = 0; i < 4; i++) {
        int hw = hw0 + threadIdx.y + i * 8;
        g_xn[((size_t)t * HW_DIM + hw) * C_DIM + c0 + threadIdx.x] =
            __float2half_rn(tile[threadIdx.x][threadIdx.y + i * 8]);
    }
}

// ---------------------------------------------------------------------------
__global__ void __launch_bounds__(256) prep_weights(const float* __restrict__ w_q,
                                                    const float* __restrict__ w_k,
                                                    const float* __restrict__ w_v,
                                                    const float* __restrict__ w_proj) {
    int i = blockIdx.x * 256 + threadIdx.x;
    if (i < 262144) {
        g_wcat[i]          = __float2half_rn(w_q[i]);
        g_wcat[262144 + i] = __float2half_rn(w_k[i]);
        g_wcat[524288 + i] = __float2half_rn(w_v[i]);
        g_wproj[i]         = __float2half_rn(w_proj[i]);
    }
}

// ---------------------------------------------------------------------------
// setup_bias: one warp per output channel j (coalesced lane-strided loads).
// ts=0 embedding = [1]*256 ++ [0]*256. K frames ts in {-2,-1,1,2}.
// ---------------------------------------------------------------------------
__global__ void __launch_bounds__(256) setup_bias(const float* __restrict__ w_q,
                                                  const float* __restrict__ b_q,
                                                  const float* __restrict__ w_k,
                                                  const float* __restrict__ b_k) {
    int wid = threadIdx.x >> 5, lane = threadIdx.x & 31;
    int j = blockIdx.x * 8 + wid;                 // 0..511
    float aq = 0.f, a0 = 0.f, a1 = 0.f, a2 = 0.f, a3 = 0.f;
    for (int c = lane; c < 512; c += 32) {
        float wq = w_q[j * 512 + c];
        float wk = w_k[j * 512 + c];
        int ci = (c < 256) ? c : c - 256;
        float fr = __expf(-0.035977892f * (float)ci);    // ln(1e4)/256
        float s1, c1, s2, c2;
        sincosf(fr, &s1, &c1);
        sincosf(2.f * fr, &s2, &c2);
        if (c < 256) {
            aq += wq;
            a0 += c2 * wk; a1 += c1 * wk; a2 += c1 * wk; a3 += c2 * wk;
        } else {
            a0 -= s2 * wk; a1 -= s1 * wk; a2 += s1 * wk; a3 += s2 * wk;
        }
    }
    for (int o = 16; o; o >>= 1) {
        aq += __shfl_xor_sync(0xffffffffu, aq, o);
        a0 += __shfl_xor_sync(0xffffffffu, a0, o);
        a1 += __shfl_xor_sync(0xffffffffu, a1, o);
        a2 += __shfl_xor_sync(0xffffffffu, a2, o);
        a3 += __shfl_xor_sync(0xffffffffu, a3, o);
    }
    if (lane == 0) {
        g_qb[j] = aq + b_q[j];
        float bk = b_k[j];
        g_kb[0 * 512 + j] = a0 + bk;
        g_kb[1 * 512 + j] = a1 + bk;
        g_kb[2 * 512 + j] = a2 + bk;
        g_kb[3 * 512 + j] = a3 + bk;
    }
}

// ---------------------------------------------------------------------------
// FP16 GEMM: C[M,N] = A[M,512] @ B[N,512]^T, fp32 accumulate.
// 128x128x32 tiles, cp.async double buffer, 8 warps (2x4), warp tile 64x32,
// mma.sync.m16n8k16.f16. smem rows pitch 20 half2 -> conflict-free.
// ---------------------------------------------------------------------------
__device__ __forceinline__ void cpa16(uint32_t dst, const void* src) {
    asm volatile("cp.async.cg.shared.global [%0], [%1], 16;\n" :: "r"(dst), "l"(src));
}
__device__ __forceinline__ void mma_f16(float* c, const uint32_t* a, const uint32_t* b) {
    asm volatile(
        "mma.sync.aligned.m16n8k16.row.col.f32.f16.f16.f32 "
        "{%0,%1,%2,%3}, {%4,%5,%6,%7}, {%8,%9}, {%0,%1,%2,%3};"
        : "+f"(c[0]), "+f"(c[1]), "+f"(c[2]), "+f"(c[3])
        : "r"(a[0]), "r"(a[1]), "r"(a[2]), "r"(a[3]), "r"(b[0]), "r"(b[1]));
}

template <int MODE>
__global__ void __launch_bounds__(256) gemm_fp16(const float* __restrict__ xres,
                                                 float* __restrict__ out,
                                                 const float* __restrict__ b_v,
                                                 const float* __restrict__ b_proj) {
    constexpr int LDS_ = 20;                 // pitch in half2 units (80B/row)
    const __half* A = (MODE == 0) ? g_xn   : g_attn;
    const __half* B = (MODE == 0) ? g_wcat : g_wproj;

    __shared__ uint32_t As[2][128 * LDS_];   // uint32 = half2
    __shared__ uint32_t Bs[2][128 * LDS_];

    int m0 = blockIdx.y * 128;
    int n0 = blockIdx.x * 128;
    int tid = threadIdx.x;
    int wid = tid >> 5, lane = tid & 31;
    int wm = (wid & 1) * 64, wn = (wid >> 1) * 32;
    int g = lane >> 2, tg = lane & 3;

    // cp.async: K-tile = 32 halves = 4 x 16B chunks per row; 128 rows x 4 = 512
    // chunks per matrix; 256 threads -> 2 chunks each (j = 0,1).
    uint32_t asb = (uint32_t)__cvta_generic_to_shared(As);
    uint32_t bsb = (uint32_t)__cvta_generic_to_shared(Bs);
    const uint32_t bufB = 128 * LDS_ * 4;

    auto load_tile = [&](int kt, int buf) {
        #pragma unroll
        for (int j = 0; j < 2; j++) {
            int i = tid + j * 256;
            int row = i >> 2, c = i & 3;
            uint32_t soff = (uint32_t)((row * LDS_ + c * 4) * 4);
            cpa16(asb + buf * bufB + soff, A + (size_t)(m0 + row) * 512 + kt * 32 + c * 8);
            cpa16(bsb + buf * bufB + soff, B + (size_t)(n0 + row) * 512 + kt * 32 + c * 8);
        }
    };

    float acc[4][4][4];
    #pragma unroll
    for (int i = 0; i < 4; i++)
        #pragma unroll
        for (int j = 0; j < 4; j++)
            #pragma unroll
            for (int r = 0; r < 4; r++) acc[i][j][r] = 0.f;

    load_tile(0, 0);
    asm volatile("cp.async.commit_group;\n" ::);

    for (int kt = 0; kt < 16; ++kt) {        // K = 512 / 32
        if (kt < 15) {
            load_tile(kt + 1, (kt + 1) & 1);
            asm volatile("cp.async.commit_group;\n" ::);
            asm volatile("cp.async.wait_group 1;\n" ::);
        } else {
            asm volatile("cp.async.wait_group 0;\n" ::);
        }
        __syncthreads();

        const uint32_t* as = As[kt & 1];
        const uint32_t* bs = Bs[kt & 1];
        #pragma unroll
        for (int kk = 0; kk < 2; ++kk) {     // two k16 steps per 32-half tile
            int kb = kk * 8;                 // half2 col base
            uint32_t af[4][4], bf[4][2];
            #pragma unroll
            for (int im = 0; im < 4; im++) {
                int r = wm + im * 16 + g;
                af[im][0] = as[r * LDS_ + kb + tg];
                af[im][1] = as[(r + 8) * LDS_ + kb + tg];
                af[im][2] = as[r * LDS_ + kb + 4 + tg];
                af[im][3] = as[(r + 8) * LDS_ + kb + 4 + tg];
            }
            #pragma unroll
            for (int in = 0; in < 4; in++) {
                int nr = wn + in * 8 + g;
                bf[in][0] = bs[nr * LDS_ + kb + tg];
                bf[in][1] = bs[nr * LDS_ + kb + 4 + tg];
            }
            #pragma unroll
            for (int im = 0; im < 4; im++)
                #pragma unroll
                for (int in = 0; in < 4; in++)
                    mma_f16(acc[im][in], af[im], bf[in]);
        }
        __syncthreads();
    }

    // epilogue (same fragment layout as m16n8k8: rows g/g+8, cols 2tg,2tg+1)
    #pragma unroll
    for (int im = 0; im < 4; im++) {
        #pragma unroll
        for (int in = 0; in < 4; in++) {
            int r = m0 + wm + im * 16 + g;
            int c = n0 + wn + in * 8 + tg * 2;
            if (MODE == 0) {
                auto bias = [&](int cc) -> float {
                    return (cc < 512) ? g_qb[cc] : ((cc < 1024) ? 0.f : b_v[cc - 1024]);
                };
                float2 v0 = make_float2(acc[im][in][0] + bias(c),
                                        acc[im][in][1] + bias(c + 1));
                float2 v1 = make_float2(acc[im][in][2] + bias(c),
                                        acc[im][in][3] + bias(c + 1));
                *(float2*)&g_qkv[(size_t)r * NQKV + c] = v0;
                *(float2*)&g_qkv[(size_t)(r + 8) * NQKV + c] = v1;
            } else {
                #pragma unroll
                for (int dr = 0; dr < 2; dr++) {
                    int rr = r + dr * 8;
                    int tt = rr >> 10, hw = rr & 1023;
                    #pragma unroll
                    for (int dc = 0; dc < 2; dc++) {
                        int cc = c + dc;
                        size_t oi = ((size_t)tt * C_DIM + cc) * HW_DIM + hw;
                        out[oi] = acc[im][in][dr * 2 + dc] + b_proj[cc] + xres[oi];
                    }
                }
            }
        }
    }
}

// ---------------------------------------------------------------------------
// Attention: one warp per token, float2-vectorized; fp16 output for proj GEMM.
// b_v folded in GEMM epilogue (softmax weights sum to 1).
// ---------------------------------------------------------------------------
__global__ void __launch_bounds__(256) attn_kernel() {
    int wid = threadIdx.x >> 5, lane = threadIdx.x & 31;
    int token = blockIdx.x * 8 + wid;
    int t = token >> 10, hw = token & 1023;
    const int offs[4] = {-2, -1, 1, 2};
    size_t kvbase[4];
    #pragma unroll
    for (int fi = 0; fi < 4; fi++) {
        int ts = t + offs[fi];
        ts = ts < 0 ? 0 : (ts > 15 ? 15 : ts);
        kvbase[fi] = (size_t)((ts << 10) | hw) * NQKV;
    }
    const float2* Q2 = (const float2*)(g_qkv + (size_t)token * NQKV);
    __half2* O2 = (__half2*)(g_attn + (size_t)token * C_DIM);

    #pragma unroll
    for (int h = 0; h < 8; ++h) {
        int cb2 = h * 32;                          // float2 index base
        float2 q = Q2[cb2 + lane];
        float s[4];
        #pragma unroll
        for (int fi = 0; fi < 4; fi++) {
            const float2* K2  = (const float2*)(g_qkv + kvbase[fi] + 512) + cb2;
            const float2* KB2 = (const float2*)(g_kb + fi * 512) + cb2;
            float2 k = K2[lane], kb = KB2[lane];
            float p = q.x * (k.x + kb.x) + q.y * (k.y + kb.y);
            for (int o = 16; o; o >>= 1) p += __shfl_xor_sync(0xffffffffu, p, o);
            s[fi] = p * 0.125f;                    // dh^-0.5, dh=64
        }
        float m = fmaxf(fmaxf(s[0], s[1]), fmaxf(s[2], s[3]));
        float e[4], sum = 0.f;
        #pragma unroll
        for (int fi = 0; fi < 4; fi++) { e[fi] = __expf(s[fi] - m); sum += e[fi]; }
        float inv = 1.f / sum;
        float ax = 0.f, ay = 0.f;
        #pragma unroll
        for (int fi = 0; fi < 4; fi++) {
            const float2* V2 = (const float2*)(g_qkv + kvbase[fi] + 1024) + cb2;
            float2 v = V2[lane];
            float p = e[fi] * inv;
            ax += p * v.x;
            ay += p * v.y;
        }
        O2[cb2 + lane] = __floats2half2_rn(ax, ay);
    }
}

// ---------------------------------------------------------------------------
extern "C" void kernel_launch(void* const* d_in, const int* in_sizes, int n_in,
                              void* d_out, int out_size) {
    const float* x       = (const float*)d_in[0];
    const float* w_q     = (const float*)d_in[1];
    const float* b_q     = (const float*)d_in[2];
    const float* w_k     = (const float*)d_in[3];
    const float* b_k     = (const float*)d_in[4];
    const float* w_v     = (const float*)d_in[5];
    const float* b_v     = (const float*)d_in[6];
    const float* w_proj  = (const float*)d_in[7];
    const float* b_proj  = (const float*)d_in[8];
    const float* gn_s    = (const float*)d_in[9];
    const float* gn_b    = (const float*)d_in[10];
    float* out = (float*)d_out;

    prep_weights<<<1024, 256>>>(w_q, w_k, w_v, w_proj);
    setup_bias<<<64, 256>>>(w_q, b_q, w_k, b_k);
    gn_stats<<<512, 256>>>(x);
    gn_apply<<<dim3(32, 16, 16), dim3(32, 8)>>>(x, gn_s, gn_b);
    gemm_fp16<0><<<dim3(12, 128), 256>>>(nullptr, nullptr, b_v, nullptr);
    attn_kernel<<<2048, 256>>>();
    gemm_fp16<1><<<dim3(4, 128), 256>>>(x, out, nullptr, b_proj);
}

// round 7
// speedup vs baseline: 4.7428x; 1.0627x over previous
#include <cuda_runtime.h>
#include <cuda_fp16.h>
#include <cstdint>

// ---------------------------------------------------------------------------
// TemporalAttention, B200 (compute_100 target -> legacy mma.sync path).
// R7 = R6 with gn_stats coverage bug fixed (16 float4 iters, full 16384 span).
// ---------------------------------------------------------------------------

#define T_DIM   16
#define C_DIM   512
#define HW_DIM  1024
#define NTOK    16384
#define NQKV    1536
#define NGRP    32
#define GN_EPS  1e-5f

__device__ __half g_xn  [NTOK * C_DIM];
__device__ __half g_qkv [NTOK * NQKV];      // fp16: halves attn + epilogue traffic
__device__ __half g_attn[NTOK * C_DIM];
__device__ __half g_wcat[NQKV * C_DIM];
__device__ __half g_wproj[C_DIM * C_DIM];
__device__ float  g_mu[512];
__device__ float  g_rs[512];
__device__ float  g_qb[C_DIM];
__device__ float  g_kb[4 * C_DIM];

// ---------------------------------------------------------------------------
__global__ void __launch_bounds__(256) gn_stats(const float* __restrict__ x) {
    int b = blockIdx.x;                       // t*32 + g
    const float4* base = (const float4*)(x + (size_t)b * 16384);
    float s = 0.f, s2 = 0.f;
    #pragma unroll
    for (int i = 0; i < 16; i++) {            // 16 * 256 * 4 = 16384 floats
        float4 v = base[threadIdx.x + i * 256];
        s  += v.x + v.y + v.z + v.w;
        s2 += v.x * v.x + v.y * v.y + v.z * v.z + v.w * v.w;
    }
    for (int o = 16; o; o >>= 1) {
        s  += __shfl_xor_sync(0xffffffffu, s,  o);
        s2 += __shfl_xor_sync(0xffffffffu, s2, o);
    }
    __shared__ float rs[8], rs2[8];
    int wid = threadIdx.x >> 5;
    if ((threadIdx.x & 31) == 0) { rs[wid] = s; rs2[wid] = s2; }
    __syncthreads();
    if (threadIdx.x == 0) {
        float a = 0.f, a2 = 0.f;
        #pragma unroll
        for (int i = 0; i < 8; i++) { a += rs[i]; a2 += rs2[i]; }
        float mu  = a  * (1.f / 16384.f);
        float var = a2 * (1.f / 16384.f) - mu * mu;
        g_mu[b] = mu;
        g_rs[b] = rsqrtf(var + GN_EPS);
    }
}

// ---------------------------------------------------------------------------
// GN apply + transpose [t,c,hw] -> [token, c], fp16 output
// ---------------------------------------------------------------------------
__global__ void __launch_bounds__(256) gn_apply(const float* __restrict__ x,
                                                const float* __restrict__ gs,
                                                const float* __restrict__ gb) {
    __shared__ float tile[32][33];
    int t   = blockIdx.z;
    int c0  = blockIdx.y * 32;
    int hw0 = blockIdx.x * 32;
    #pragma unroll
    for (int i = 0; i < 4; i++) {
        int c = c0 + threadIdx.y + i * 8;
        float v = x[((size_t)t * C_DIM + c) * HW_DIM + hw0 + threadIdx.x];
        int grp = c >> 4;
        v = (v - g_mu[t * NGRP + grp]) * g_rs[t * NGRP + grp] * gs[c] + gb[c];
        tile[threadIdx.y + i * 8][threadIdx.x] = v;
    }
    __syncthreads();
    #pragma unroll
    for (int i = 0; i < 4; i++) {
        int hw = hw0 + threadIdx.y + i * 8;
        g_xn[((size_t)t * HW_DIM + hw) * C_DIM + c0 + threadIdx.x] =
            __float2half_rn(tile[threadIdx.x][threadIdx.y + i * 8]);
    }
}

// ---------------------------------------------------------------------------
__global__ void __launch_bounds__(256) prep_weights(const float* __restrict__ w_q,
                                                    const float* __restrict__ w_k,
                                                    const float* __restrict__ w_v,
                                                    const float* __restrict__ w_proj) {
    int i = blockIdx.x * 256 + threadIdx.x;
    if (i < 262144) {
        g_wcat[i]          = __float2half_rn(w_q[i]);
        g_wcat[262144 + i] = __float2half_rn(w_k[i]);
        g_wcat[524288 + i] = __float2half_rn(w_v[i]);
        g_wproj[i]         = __float2half_rn(w_proj[i]);
    }
}

// ---------------------------------------------------------------------------
// setup_bias: one warp per output channel j (coalesced lane-strided loads).
// ts=0 embedding = [1]*256 ++ [0]*256. K frames ts in {-2,-1,1,2}.
// ---------------------------------------------------------------------------
__global__ void __launch_bounds__(256) setup_bias(const float* __restrict__ w_q,
                                                  const float* __restrict__ b_q,
                                                  const float* __restrict__ w_k,
                                                  const float* __restrict__ b_k) {
    int wid = threadIdx.x >> 5, lane = threadIdx.x & 31;
    int j = blockIdx.x * 8 + wid;                 // 0..511
    float aq = 0.f, a0 = 0.f, a1 = 0.f, a2 = 0.f, a3 = 0.f;
    for (int c = lane; c < 512; c += 32) {
        float wq = w_q[j * 512 + c];
        float wk = w_k[j * 512 + c];
        int ci = (c < 256) ? c : c - 256;
        float fr = __expf(-0.035977892f * (float)ci);    // ln(1e4)/256
        float s1, c1, s2, c2;
        sincosf(fr, &s1, &c1);
        sincosf(2.f * fr, &s2, &c2);
        if (c < 256) {
            aq += wq;
            a0 += c2 * wk; a1 += c1 * wk; a2 += c1 * wk; a3 += c2 * wk;
        } else {
            a0 -= s2 * wk; a1 -= s1 * wk; a2 += s1 * wk; a3 += s2 * wk;
        }
    }
    for (int o = 16; o; o >>= 1) {
        aq += __shfl_xor_sync(0xffffffffu, aq, o);
        a0 += __shfl_xor_sync(0xffffffffu, a0, o);
        a1 += __shfl_xor_sync(0xffffffffu, a1, o);
        a2 += __shfl_xor_sync(0xffffffffu, a2, o);
        a3 += __shfl_xor_sync(0xffffffffu, a3, o);
    }
    if (lane == 0) {
        g_qb[j] = aq + b_q[j];
        float bk = b_k[j];
        g_kb[0 * 512 + j] = a0 + bk;
        g_kb[1 * 512 + j] = a1 + bk;
        g_kb[2 * 512 + j] = a2 + bk;
        g_kb[3 * 512 + j] = a3 + bk;
    }
}

// ---------------------------------------------------------------------------
// FP16 GEMM: C[M,N] = A[M,512] @ B[N,512]^T, fp32 accumulate.
// 128x128x32 tiles, cp.async double buffer, 8 warps (2x4), warp tile 64x32,
// mma.sync.m16n8k16 + ldmatrix.x4 fragment loads. Pitch-20 uint32 rows.
// ---------------------------------------------------------------------------
__device__ __forceinline__ void cpa16(uint32_t dst, const void* src) {
    asm volatile("cp.async.cg.shared.global [%0], [%1], 16;\n" :: "r"(dst), "l"(src));
}
__device__ __forceinline__ void mma_f16(float* c, const uint32_t* a, const uint32_t* b) {
    asm volatile(
        "mma.sync.aligned.m16n8k16.row.col.f32.f16.f16.f32 "
        "{%0,%1,%2,%3}, {%4,%5,%6,%7}, {%8,%9}, {%0,%1,%2,%3};"
        : "+f"(c[0]), "+f"(c[1]), "+f"(c[2]), "+f"(c[3])
        : "r"(a[0]), "r"(a[1]), "r"(a[2]), "r"(a[3]), "r"(b[0]), "r"(b[1]));
}
__device__ __forceinline__ void ldsm4(uint32_t& r0, uint32_t& r1, uint32_t& r2,
                                      uint32_t& r3, uint32_t a) {
    asm volatile("ldmatrix.sync.aligned.m8n8.x4.shared.b16 {%0,%1,%2,%3}, [%4];"
                 : "=r"(r0), "=r"(r1), "=r"(r2), "=r"(r3) : "r"(a));
}

template <int MODE>
__global__ void __launch_bounds__(256) gemm_fp16(const float* __restrict__ xres,
                                                 float* __restrict__ out,
                                                 const float* __restrict__ b_v,
                                                 const float* __restrict__ b_proj) {
    constexpr int LDS_ = 20;                 // pitch in half2 units (80B/row)
    const __half* A = (MODE == 0) ? g_xn   : g_attn;
    const __half* B = (MODE == 0) ? g_wcat : g_wproj;

    __shared__ uint32_t As[2][128 * LDS_];   // uint32 = half2
    __shared__ uint32_t Bs[2][128 * LDS_];

    int m0 = blockIdx.y * 128;
    int n0 = blockIdx.x * 128;
    int tid = threadIdx.x;
    int wid = tid >> 5, lane = tid & 31;
    int wm = (wid & 1) * 64, wn = (wid >> 1) * 32;
    int g = lane >> 2, tg = lane & 3;

    uint32_t asb = (uint32_t)__cvta_generic_to_shared(As);
    uint32_t bsb = (uint32_t)__cvta_generic_to_shared(Bs);
    const uint32_t bufB = 128 * LDS_ * 4;

    // ldmatrix lane address components
    int a_row = wm + (lane & 15);                       // + im*16
    int a_col = (lane >> 4) << 2;                       // 0 or 4 (uint32)
    int b_row = wn + ((lane >> 4) << 3) + (lane & 7);   // + 16*pair
    int b_col = ((lane >> 3) & 1) << 2;                 // 0 or 4

    auto load_tile = [&](int kt, int buf) {
        #pragma unroll
        for (int j = 0; j < 2; j++) {
            int i = tid + j * 256;
            int row = i >> 2, c = i & 3;
            uint32_t soff = (uint32_t)((row * LDS_ + c * 4) * 4);
            cpa16(asb + buf * bufB + soff, A + (size_t)(m0 + row) * 512 + kt * 32 + c * 8);
            cpa16(bsb + buf * bufB + soff, B + (size_t)(n0 + row) * 512 + kt * 32 + c * 8);
        }
    };

    float acc[4][4][4];
    #pragma unroll
    for (int i = 0; i < 4; i++)
        #pragma unroll
        for (int j = 0; j < 4; j++)
            #pragma unroll
            for (int r = 0; r < 4; r++) acc[i][j][r] = 0.f;

    load_tile(0, 0);
    asm volatile("cp.async.commit_group;\n" ::);

    for (int kt = 0; kt < 16; ++kt) {        // K = 512 / 32
        if (kt < 15) {
            load_tile(kt + 1, (kt + 1) & 1);
            asm volatile("cp.async.commit_group;\n" ::);
            asm volatile("cp.async.wait_group 1;\n" ::);
        } else {
            asm volatile("cp.async.wait_group 0;\n" ::);
        }
        __syncthreads();

        uint32_t abase = asb + (uint32_t)(kt & 1) * bufB;
        uint32_t bbase = bsb + (uint32_t)(kt & 1) * bufB;
        #pragma unroll
        for (int kk = 0; kk < 2; ++kk) {     // two k16 steps per 32-half tile
            int kb = kk * 8;                 // half2 col base
            uint32_t af[4][4], bf[4][2];
            #pragma unroll
            for (int im = 0; im < 4; im++)
                ldsm4(af[im][0], af[im][1], af[im][2], af[im][3],
                      abase + (uint32_t)(((a_row + im * 16) * LDS_ + kb + a_col) * 4));
            #pragma unroll
            for (int p = 0; p < 2; p++)
                ldsm4(bf[2 * p][0], bf[2 * p][1], bf[2 * p + 1][0], bf[2 * p + 1][1],
                      bbase + (uint32_t)(((b_row + 16 * p) * LDS_ + kb + b_col) * 4));
            #pragma unroll
            for (int im = 0; im < 4; im++)
                #pragma unroll
                for (int in = 0; in < 4; in++)
                    mma_f16(acc[im][in], af[im], bf[in]);
        }
        __syncthreads();
    }

    // epilogue (fragment rows g/g+8, cols 2tg, 2tg+1)
    #pragma unroll
    for (int im = 0; im < 4; im++) {
        #pragma unroll
        for (int in = 0; in < 4; in++) {
            int r = m0 + wm + im * 16 + g;
            int c = n0 + wn + in * 8 + tg * 2;
            if (MODE == 0) {
                auto bias = [&](int cc) -> float {
                    return (cc < 512) ? g_qb[cc] : ((cc < 1024) ? 0.f : b_v[cc - 1024]);
                };
                float b0 = bias(c), b1 = bias(c + 1);
                *(__half2*)&g_qkv[(size_t)r * NQKV + c] =
                    __floats2half2_rn(acc[im][in][0] + b0, acc[im][in][1] + b1);
                *(__half2*)&g_qkv[(size_t)(r + 8) * NQKV + c] =
                    __floats2half2_rn(acc[im][in][2] + b0, acc[im][in][3] + b1);
            } else {
                #pragma unroll
                for (int dr = 0; dr < 2; dr++) {
                    int rr = r + dr * 8;
                    int tt = rr >> 10, hw = rr & 1023;
                    #pragma unroll
                    for (int dc = 0; dc < 2; dc++) {
                        int cc = c + dc;
                        size_t oi = ((size_t)tt * C_DIM + cc) * HW_DIM + hw;
                        out[oi] = acc[im][in][dr * 2 + dc] + b_proj[cc] + xres[oi];
                    }
                }
            }
        }
    }
}

// ---------------------------------------------------------------------------
// Attention: one warp per token; fp16 Q/K/V, fp32 math, fp16 out.
// b_v folded in GEMM epilogue (softmax weights sum to 1).
// ---------------------------------------------------------------------------
__global__ void __launch_bounds__(256) attn_kernel() {
    int wid = threadIdx.x >> 5, lane = threadIdx.x & 31;
    int token = blockIdx.x * 8 + wid;
    int t = token >> 10, hw = token & 1023;
    const int offs[4] = {-2, -1, 1, 2};
    size_t kvbase[4];
    #pragma unroll
    for (int fi = 0; fi < 4; fi++) {
        int ts = t + offs[fi];
        ts = ts < 0 ? 0 : (ts > 15 ? 15 : ts);
        kvbase[fi] = (size_t)((ts << 10) | hw) * NQKV;
    }
    const __half2* Q2 = (const __half2*)(g_qkv + (size_t)token * NQKV);
    __half2* O2 = (__half2*)(g_attn + (size_t)token * C_DIM);

    #pragma unroll
    for (int h = 0; h < 8; ++h) {
        int cb2 = h * 32;                          // half2 index base
        float2 q = __half22float2(Q2[cb2 + lane]);
        float s[4];
        #pragma unroll
        for (int fi = 0; fi < 4; fi++) {
            const __half2* K2 = (const __half2*)(g_qkv + kvbase[fi] + 512) + cb2;
            const float2* KB2 = (const float2*)(g_kb + fi * 512) + cb2;
            float2 k = __half22float2(K2[lane]);
            float2 kb = KB2[lane];
            float p = q.x * (k.x + kb.x) + q.y * (k.y + kb.y);
            for (int o = 16; o; o >>= 1) p += __shfl_xor_sync(0xffffffffu, p, o);
            s[fi] = p * 0.125f;                    // dh^-0.5, dh=64
        }
        float m = fmaxf(fmaxf(s[0], s[1]), fmaxf(s[2], s[3]));
        float e[4], sum = 0.f;
        #pragma unroll
        for (int fi = 0; fi < 4; fi++) { e[fi] = __expf(s[fi] - m); sum += e[fi]; }
        float inv = 1.f / sum;
        float ax = 0.f, ay = 0.f;
        #pragma unroll
        for (int fi = 0; fi < 4; fi++) {
            const __half2* V2 = (const __half2*)(g_qkv + kvbase[fi] + 1024) + cb2;
            float2 v = __half22float2(V2[lane]);
            float p = e[fi] * inv;
            ax += p * v.x;
            ay += p * v.y;
        }
        O2[cb2 + lane] = __floats2half2_rn(ax, ay);
    }
}

// ---------------------------------------------------------------------------
extern "C" void kernel_launch(void* const* d_in, const int* in_sizes, int n_in,
                              void* d_out, int out_size) {
    const float* x       = (const float*)d_in[0];
    const float* w_q     = (const float*)d_in[1];
    const float* b_q     = (const float*)d_in[2];
    const float* w_k     = (const float*)d_in[3];
    const float* b_k     = (const float*)d_in[4];
    const float* w_v     = (const float*)d_in[5];
    const float* b_v     = (const float*)d_in[6];
    const float* w_proj  = (const float*)d_in[7];
    const float* b_proj  = (const float*)d_in[8];
    const float* gn_s    = (const float*)d_in[9];
    const float* gn_b    = (const float*)d_in[10];
    float* out = (float*)d_out;

    prep_weights<<<1024, 256>>>(w_q, w_k, w_v, w_proj);
    setup_bias<<<64, 256>>>(w_q, b_q, w_k, b_k);
    gn_stats<<<512, 256>>>(x);
    gn_apply<<<dim3(32, 16, 16), dim3(32, 8)>>>(x, gn_s, gn_b);
    gemm_fp16<0><<<dim3(12, 128), 256>>>(nullptr, nullptr, b_v, nullptr);
    attn_kernel<<<2048, 256>>>();
    gemm_fp16<1><<<dim3(4, 128), 256>>>(x, out, nullptr, b_proj);
}

// round 8
// speedup vs baseline: 4.7482x; 1.0011x over previous
#include <cuda_runtime.h>
#include <cuda_fp16.h>
#include <cstdint>

// ---------------------------------------------------------------------------
// TemporalAttention, B200 (compute_100 target -> legacy mma.sync path).
// R8: launch reorder (gemm0 into profiled slot), biases folded into attn,
//     prep_weights+setup_bias fused. GEMM core unchanged from R7.
// Order: gn_stats, gn_apply, prep_bias, gemm0, attn, gemm1
// ---------------------------------------------------------------------------

#define T_DIM   16
#define C_DIM   512
#define HW_DIM  1024
#define NTOK    16384
#define NQKV    1536
#define NGRP    32
#define GN_EPS  1e-5f

__device__ __half g_xn  [NTOK * C_DIM];
__device__ __half g_qkv [NTOK * NQKV];      // raw Q|K|V (biases applied in attn)
__device__ __half g_attn[NTOK * C_DIM];
__device__ __half g_wcat[NQKV * C_DIM];
__device__ __half g_wproj[C_DIM * C_DIM];
__device__ float  g_mu[512];
__device__ float  g_rs[512];
__device__ float  g_qb[C_DIM];              // b_q + t_mid @ Wq^T
__device__ float  g_kb[4 * C_DIM];          // b_k + t_rest[fi] @ Wk^T

// ---------------------------------------------------------------------------
__global__ void __launch_bounds__(256) gn_stats(const float* __restrict__ x) {
    int b = blockIdx.x;                       // t*32 + g
    const float4* base = (const float4*)(x + (size_t)b * 16384);
    float s = 0.f, s2 = 0.f;
    #pragma unroll
    for (int i = 0; i < 16; i++) {            // 16 * 256 * 4 = 16384 floats
        float4 v = base[threadIdx.x + i * 256];
        s  += v.x + v.y + v.z + v.w;
        s2 += v.x * v.x + v.y * v.y + v.z * v.z + v.w * v.w;
    }
    for (int o = 16; o; o >>= 1) {
        s  += __shfl_xor_sync(0xffffffffu, s,  o);
        s2 += __shfl_xor_sync(0xffffffffu, s2, o);
    }
    __shared__ float rs[8], rs2[8];
    int wid = threadIdx.x >> 5;
    if ((threadIdx.x & 31) == 0) { rs[wid] = s; rs2[wid] = s2; }
    __syncthreads();
    if (threadIdx.x == 0) {
        float a = 0.f, a2 = 0.f;
        #pragma unroll
        for (int i = 0; i < 8; i++) { a += rs[i]; a2 += rs2[i]; }
        float mu  = a  * (1.f / 16384.f);
        float var = a2 * (1.f / 16384.f) - mu * mu;
        g_mu[b] = mu;
        g_rs[b] = rsqrtf(var + GN_EPS);
    }
}

// ---------------------------------------------------------------------------
// GN apply + transpose [t,c,hw] -> [token, c], fp16 output
// ---------------------------------------------------------------------------
__global__ void __launch_bounds__(256) gn_apply(const float* __restrict__ x,
                                                const float* __restrict__ gs,
                                                const float* __restrict__ gb) {
    __shared__ float tile[32][33];
    int t   = blockIdx.z;
    int c0  = blockIdx.y * 32;
    int hw0 = blockIdx.x * 32;
    #pragma unroll
    for (int i = 0; i < 4; i++) {
        int c = c0 + threadIdx.y + i * 8;
        float v = x[((size_t)t * C_DIM + c) * HW_DIM + hw0 + threadIdx.x];
        int grp = c >> 4;
        v = (v - g_mu[t * NGRP + grp]) * g_rs[t * NGRP + grp] * gs[c] + gb[c];
        tile[threadIdx.y + i * 8][threadIdx.x] = v;
    }
    __syncthreads();
    #pragma unroll
    for (int i = 0; i < 4; i++) {
        int hw = hw0 + threadIdx.y + i * 8;
        g_xn[((size_t)t * HW_DIM + hw) * C_DIM + c0 + threadIdx.x] =
            __float2half_rn(tile[threadIdx.x][threadIdx.y + i * 8]);
    }
}

// ---------------------------------------------------------------------------
// prep_bias: blocks [0,1024) convert weights to fp16; blocks [1024,1088)
// compute qb/kb (one warp per output channel, coalesced + shfl reduce).
// ---------------------------------------------------------------------------
__global__ void __launch_bounds__(256) prep_bias(const float* __restrict__ w_q,
                                                 const float* __restrict__ w_k,
                                                 const float* __restrict__ w_v,
                                                 const float* __restrict__ w_proj,
                                                 const float* __restrict__ b_q,
                                                 const float* __restrict__ b_k) {
    if (blockIdx.x < 1024) {
        int i = blockIdx.x * 256 + threadIdx.x;
        g_wcat[i]          = __float2half_rn(w_q[i]);
        g_wcat[262144 + i] = __float2half_rn(w_k[i]);
        g_wcat[524288 + i] = __float2half_rn(w_v[i]);
        g_wproj[i]         = __float2half_rn(w_proj[i]);
        return;
    }
    int wid = threadIdx.x >> 5, lane = threadIdx.x & 31;
    int j = (blockIdx.x - 1024) * 8 + wid;        // 0..511
    float aq = 0.f, a0 = 0.f, a1 = 0.f, a2 = 0.f, a3 = 0.f;
    for (int c = lane; c < 512; c += 32) {
        float wq = w_q[j * 512 + c];
        float wk = w_k[j * 512 + c];
        int ci = (c < 256) ? c : c - 256;
        float fr = __expf(-0.035977892f * (float)ci);    // ln(1e4)/256
        float s1, c1, s2, c2;
        sincosf(fr, &s1, &c1);
        sincosf(2.f * fr, &s2, &c2);
        if (c < 256) {
            aq += wq;
            a0 += c2 * wk; a1 += c1 * wk; a2 += c1 * wk; a3 += c2 * wk;
        } else {
            a0 -= s2 * wk; a1 -= s1 * wk; a2 += s1 * wk; a3 += s2 * wk;
        }
    }
    for (int o = 16; o; o >>= 1) {
        aq += __shfl_xor_sync(0xffffffffu, aq, o);
        a0 += __shfl_xor_sync(0xffffffffu, a0, o);
        a1 += __shfl_xor_sync(0xffffffffu, a1, o);
        a2 += __shfl_xor_sync(0xffffffffu, a2, o);
        a3 += __shfl_xor_sync(0xffffffffu, a3, o);
    }
    if (lane == 0) {
        g_qb[j] = aq + b_q[j];
        float bk = b_k[j];
        g_kb[0 * 512 + j] = a0 + bk;
        g_kb[1 * 512 + j] = a1 + bk;
        g_kb[2 * 512 + j] = a2 + bk;
        g_kb[3 * 512 + j] = a3 + bk;
    }
}

// ---------------------------------------------------------------------------
// FP16 GEMM: C[M,N] = A[M,512] @ B[N,512]^T, fp32 accumulate.
// 128x128x32 tiles, cp.async double buffer, 8 warps (2x4), warp tile 64x32,
// mma.sync.m16n8k16 + ldmatrix.x4. Pitch-20 uint32 rows.
// MODE 0 epilogue: raw fp16 store. MODE 1: out = acc + b_proj + x.
// ---------------------------------------------------------------------------
__device__ __forceinline__ void cpa16(uint32_t dst, const void* src) {
    asm volatile("cp.async.cg.shared.global [%0], [%1], 16;\n" :: "r"(dst), "l"(src));
}
__device__ __forceinline__ void mma_f16(float* c, const uint32_t* a, const uint32_t* b) {
    asm volatile(
        "mma.sync.aligned.m16n8k16.row.col.f32.f16.f16.f32 "
        "{%0,%1,%2,%3}, {%4,%5,%6,%7}, {%8,%9}, {%0,%1,%2,%3};"
        : "+f"(c[0]), "+f"(c[1]), "+f"(c[2]), "+f"(c[3])
        : "r"(a[0]), "r"(a[1]), "r"(a[2]), "r"(a[3]), "r"(b[0]), "r"(b[1]));
}
__device__ __forceinline__ void ldsm4(uint32_t& r0, uint32_t& r1, uint32_t& r2,
                                      uint32_t& r3, uint32_t a) {
    asm volatile("ldmatrix.sync.aligned.m8n8.x4.shared.b16 {%0,%1,%2,%3}, [%4];"
                 : "=r"(r0), "=r"(r1), "=r"(r2), "=r"(r3) : "r"(a));
}

template <int MODE>
__global__ void __launch_bounds__(256) gemm_fp16(const float* __restrict__ xres,
                                                 float* __restrict__ out,
                                                 const float* __restrict__ b_proj) {
    constexpr int LDS_ = 20;                 // pitch in half2 units (80B/row)
    const __half* A = (MODE == 0) ? g_xn   : g_attn;
    const __half* B = (MODE == 0) ? g_wcat : g_wproj;

    __shared__ uint32_t As[2][128 * LDS_];   // uint32 = half2
    __shared__ uint32_t Bs[2][128 * LDS_];

    int m0 = blockIdx.y * 128;
    int n0 = blockIdx.x * 128;
    int tid = threadIdx.x;
    int wid = tid >> 5, lane = tid & 31;
    int wm = (wid & 1) * 64, wn = (wid >> 1) * 32;
    int g = lane >> 2, tg = lane & 3;

    uint32_t asb = (uint32_t)__cvta_generic_to_shared(As);
    uint32_t bsb = (uint32_t)__cvta_generic_to_shared(Bs);
    const uint32_t bufB = 128 * LDS_ * 4;

    // ldmatrix lane address components
    int a_row = wm + (lane & 15);                       // + im*16
    int a_col = (lane >> 4) << 2;                       // 0 or 4 (uint32)
    int b_row = wn + ((lane >> 4) << 3) + (lane & 7);   // + 16*pair
    int b_col = ((lane >> 3) & 1) << 2;                 // 0 or 4

    auto load_tile = [&](int kt, int buf) {
        #pragma unroll
        for (int j = 0; j < 2; j++) {
            int i = tid + j * 256;
            int row = i >> 2, c = i & 3;
            uint32_t soff = (uint32_t)((row * LDS_ + c * 4) * 4);
            cpa16(asb + buf * bufB + soff, A + (size_t)(m0 + row) * 512 + kt * 32 + c * 8);
            cpa16(bsb + buf * bufB + soff, B + (size_t)(n0 + row) * 512 + kt * 32 + c * 8);
        }
    };

    float acc[4][4][4];
    #pragma unroll
    for (int i = 0; i < 4; i++)
        #pragma unroll
        for (int j = 0; j < 4; j++)
            #pragma unroll
            for (int r = 0; r < 4; r++) acc[i][j][r] = 0.f;

    load_tile(0, 0);
    asm volatile("cp.async.commit_group;\n" ::);

    for (int kt = 0; kt < 16; ++kt) {        // K = 512 / 32
        if (kt < 15) {
            load_tile(kt + 1, (kt + 1) & 1);
            asm volatile("cp.async.commit_group;\n" ::);
            asm volatile("cp.async.wait_group 1;\n" ::);
        } else {
            asm volatile("cp.async.wait_group 0;\n" ::);
        }
        __syncthreads();

        uint32_t abase = asb + (uint32_t)(kt & 1) * bufB;
        uint32_t bbase = bsb + (uint32_t)(kt & 1) * bufB;
        #pragma unroll
        for (int kk = 0; kk < 2; ++kk) {     // two k16 steps per 32-half tile
            int kb = kk * 8;                 // half2 col base
            uint32_t af[4][4], bf[4][2];
            #pragma unroll
            for (int im = 0; im < 4; im++)
                ldsm4(af[im][0], af[im][1], af[im][2], af[im][3],
                      abase + (uint32_t)(((a_row + im * 16) * LDS_ + kb + a_col) * 4));
            #pragma unroll
            for (int p = 0; p < 2; p++)
                ldsm4(bf[2 * p][0], bf[2 * p][1], bf[2 * p + 1][0], bf[2 * p + 1][1],
                      bbase + (uint32_t)(((b_row + 16 * p) * LDS_ + kb + b_col) * 4));
            #pragma unroll
            for (int im = 0; im < 4; im++)
                #pragma unroll
                for (int in = 0; in < 4; in++)
                    mma_f16(acc[im][in], af[im], bf[in]);
        }
        __syncthreads();
    }

    // epilogue (fragment rows g/g+8, cols 2tg, 2tg+1)
    #pragma unroll
    for (int im = 0; im < 4; im++) {
        #pragma unroll
        for (int in = 0; in < 4; in++) {
            int r = m0 + wm + im * 16 + g;
            int c = n0 + wn + in * 8 + tg * 2;
            if (MODE == 0) {
                *(__half2*)&g_qkv[(size_t)r * NQKV + c] =
                    __floats2half2_rn(acc[im][in][0], acc[im][in][1]);
                *(__half2*)&g_qkv[(size_t)(r + 8) * NQKV + c] =
                    __floats2half2_rn(acc[im][in][2], acc[im][in][3]);
            } else {
                #pragma unroll
                for (int dr = 0; dr < 2; dr++) {
                    int rr = r + dr * 8;
                    int tt = rr >> 10, hw = rr & 1023;
                    #pragma unroll
                    for (int dc = 0; dc < 2; dc++) {
                        int cc = c + dc;
                        size_t oi = ((size_t)tt * C_DIM + cc) * HW_DIM + hw;
                        out[oi] = acc[im][in][dr * 2 + dc] + b_proj[cc] + xres[oi];
                    }
                }
            }
        }
    }
}

// ---------------------------------------------------------------------------
// Attention: one warp per token; fp16 raw Q/K/V; all biases folded here in
// fp32: score = (q+qb)·(k+kb);  out = sum_f p_f v_f + b_v (sum p = 1).
// ---------------------------------------------------------------------------
__global__ void __launch_bounds__(256) attn_kernel(const float* __restrict__ b_v) {
    int wid = threadIdx.x >> 5, lane = threadIdx.x & 31;
    int token = blockIdx.x * 8 + wid;
    int t = token >> 10, hw = token & 1023;
    const int offs[4] = {-2, -1, 1, 2};
    size_t kvbase[4];
    #pragma unroll
    for (int fi = 0; fi < 4; fi++) {
        int ts = t + offs[fi];
        ts = ts < 0 ? 0 : (ts > 15 ? 15 : ts);
        kvbase[fi] = (size_t)((ts << 10) | hw) * NQKV;
    }
    const __half2* Q2 = (const __half2*)(g_qkv + (size_t)token * NQKV);
    __half2* O2 = (__half2*)(g_attn + (size_t)token * C_DIM);

    #pragma unroll
    for (int h = 0; h < 8; ++h) {
        int cb2 = h * 32;                          // half2 index base
        float2 qb = ((const float2*)g_qb)[cb2 + lane];
        float2 q = __half22float2(Q2[cb2 + lane]);
        q.x += qb.x; q.y += qb.y;
        float s[4];
        #pragma unroll
        for (int fi = 0; fi < 4; fi++) {
            const __half2* K2 = (const __half2*)(g_qkv + kvbase[fi] + 512) + cb2;
            const float2* KB2 = (const float2*)(g_kb + fi * 512) + cb2;
            float2 k = __half22float2(K2[lane]);
            float2 kb = KB2[lane];
            float p = q.x * (k.x + kb.x) + q.y * (k.y + kb.y);
            for (int o = 16; o; o >>= 1) p += __shfl_xor_sync(0xffffffffu, p, o);
            s[fi] = p * 0.125f;                    // dh^-0.5, dh=64
        }
        float m = fmaxf(fmaxf(s[0], s[1]), fmaxf(s[2], s[3]));
        float e[4], sum = 0.f;
        #pragma unroll
        for (int fi = 0; fi < 4; fi++) { e[fi] = __expf(s[fi] - m); sum += e[fi]; }
        float inv = 1.f / sum;
        float ax = 0.f, ay = 0.f;
        #pragma unroll
        for (int fi = 0; fi < 4; fi++) {
            const __half2* V2 = (const __half2*)(g_qkv + kvbase[fi] + 1024) + cb2;
            float2 v = __half22float2(V2[lane]);
            float p = e[fi] * inv;
            ax += p * v.x;
            ay += p * v.y;
        }
        float2 bv = ((const float2*)b_v)[cb2 + lane];
        O2[cb2 + lane] = __floats2half2_rn(ax + bv.x, ay + bv.y);
    }
}

// ---------------------------------------------------------------------------
extern "C" void kernel_launch(void* const* d_in, const int* in_sizes, int n_in,
                              void* d_out, int out_size) {
    const float* x       = (const float*)d_in[0];
    const float* w_q     = (const float*)d_in[1];
    const float* b_q     = (const float*)d_in[2];
    const float* w_k     = (const float*)d_in[3];
    const float* b_k     = (const float*)d_in[4];
    const float* w_v     = (const float*)d_in[5];
    const float* b_v     = (const float*)d_in[6];
    const float* w_proj  = (const float*)d_in[7];
    const float* b_proj  = (const float*)d_in[8];
    const float* gn_s    = (const float*)d_in[9];
    const float* gn_b    = (const float*)d_in[10];
    float* out = (float*)d_out;

    gn_stats<<<512, 256>>>(x);
    gn_apply<<<dim3(32, 16, 16), dim3(32, 8)>>>(x, gn_s, gn_b);
    prep_bias<<<1088, 256>>>(w_q, w_k, w_v, w_proj, b_q, b_k);
    gemm_fp16<0><<<dim3(12, 128), 256>>>(nullptr, nullptr, nullptr);
    attn_kernel<<<2048, 256>>>(b_v);
    gemm_fp16<1><<<dim3(4, 128), 256>>>(x, out, b_proj);
}

// round 10
// speedup vs baseline: 4.8716x; 1.0260x over previous
#include <cuda_runtime.h>
#include <cuda_fp16.h>
#include <cstdint>

// ---------------------------------------------------------------------------
// TemporalAttention, B200 (compute_100 target -> legacy mma.sync path).
// R10 = R9 (4-stage cp.async pipeline, coalesced epilogues) with the
// static-guard removed from kernel_launch (harness rule compliance).
// Order: gn_stats, gn_apply, prep_bias, gemm0, attn, gemm1
// ---------------------------------------------------------------------------

#define T_DIM   16
#define C_DIM   512
#define HW_DIM  1024
#define NTOK    16384
#define NQKV    1536
#define NGRP    32
#define GN_EPS  1e-5f

__device__ __half g_xn  [NTOK * C_DIM];
__device__ __half g_qkv [NTOK * NQKV];      // raw Q|K|V (biases applied in attn)
__device__ __half g_attn[NTOK * C_DIM];
__device__ __half g_wcat[NQKV * C_DIM];
__device__ __half g_wproj[C_DIM * C_DIM];
__device__ float  g_mu[512];
__device__ float  g_rs[512];
__device__ float  g_qb[C_DIM];              // b_q + t_mid @ Wq^T
__device__ float  g_kb[4 * C_DIM];          // b_k + t_rest[fi] @ Wk^T

// ---------------------------------------------------------------------------
__global__ void __launch_bounds__(256) gn_stats(const float* __restrict__ x) {
    int b = blockIdx.x;                       // t*32 + g
    const float4* base = (const float4*)(x + (size_t)b * 16384);
    float s = 0.f, s2 = 0.f;
    #pragma unroll
    for (int i = 0; i < 16; i++) {            // 16 * 256 * 4 = 16384 floats
        float4 v = base[threadIdx.x + i * 256];
        s  += v.x + v.y + v.z + v.w;
        s2 += v.x * v.x + v.y * v.y + v.z * v.z + v.w * v.w;
    }
    for (int o = 16; o; o >>= 1) {
        s  += __shfl_xor_sync(0xffffffffu, s,  o);
        s2 += __shfl_xor_sync(0xffffffffu, s2, o);
    }
    __shared__ float rs[8], rs2[8];
    int wid = threadIdx.x >> 5;
    if ((threadIdx.x & 31) == 0) { rs[wid] = s; rs2[wid] = s2; }
    __syncthreads();
    if (threadIdx.x == 0) {
        float a = 0.f, a2 = 0.f;
        #pragma unroll
        for (int i = 0; i < 8; i++) { a += rs[i]; a2 += rs2[i]; }
        float mu  = a  * (1.f / 16384.f);
        float var = a2 * (1.f / 16384.f) - mu * mu;
        g_mu[b] = mu;
        g_rs[b] = rsqrtf(var + GN_EPS);
    }
}

// ---------------------------------------------------------------------------
// GN apply + transpose [t,c,hw] -> [token, c], fp16 output
// ---------------------------------------------------------------------------
__global__ void __launch_bounds__(256) gn_apply(const float* __restrict__ x,
                                                const float* __restrict__ gs,
                                                const float* __restrict__ gb) {
    __shared__ float tile[32][33];
    int t   = blockIdx.z;
    int c0  = blockIdx.y * 32;
    int hw0 = blockIdx.x * 32;
    #pragma unroll
    for (int i = 0; i < 4; i++) {
        int c = c0 + threadIdx.y + i * 8;
        float v = x[((size_t)t * C_DIM + c) * HW_DIM + hw0 + threadIdx.x];
        int grp = c >> 4;
        v = (v - g_mu[t * NGRP + grp]) * g_rs[t * NGRP + grp] * gs[c] + gb[c];
        tile[threadIdx.y + i * 8][threadIdx.x] = v;
    }
    __syncthreads();
    #pragma unroll
    for (int i = 0; i < 4; i++) {
        int hw = hw0 + threadIdx.y + i * 8;
        g_xn[((size_t)t * HW_DIM + hw) * C_DIM + c0 + threadIdx.x] =
            __float2half_rn(tile[threadIdx.x][threadIdx.y + i * 8]);
    }
}

// ---------------------------------------------------------------------------
// prep_bias: blocks [0,1024) convert weights to fp16; blocks [1024,1088)
// compute qb/kb (one warp per output channel, coalesced + shfl reduce).
// ---------------------------------------------------------------------------
__global__ void __launch_bounds__(256) prep_bias(const float* __restrict__ w_q,
                                                 const float* __restrict__ w_k,
                                                 const float* __restrict__ w_v,
                                                 const float* __restrict__ w_proj,
                                                 const float* __restrict__ b_q,
                                                 const float* __restrict__ b_k) {
    if (blockIdx.x < 1024) {
        int i = blockIdx.x * 256 + threadIdx.x;
        g_wcat[i]          = __float2half_rn(w_q[i]);
        g_wcat[262144 + i] = __float2half_rn(w_k[i]);
        g_wcat[524288 + i] = __float2half_rn(w_v[i]);
        g_wproj[i]         = __float2half_rn(w_proj[i]);
        return;
    }
    int wid = threadIdx.x >> 5, lane = threadIdx.x & 31;
    int j = (blockIdx.x - 1024) * 8 + wid;        // 0..511
    float aq = 0.f, a0 = 0.f, a1 = 0.f, a2 = 0.f, a3 = 0.f;
    for (int c = lane; c < 512; c += 32) {
        float wq = w_q[j * 512 + c];
        float wk = w_k[j * 512 + c];
        int ci = (c < 256) ? c : c - 256;
        float fr = __expf(-0.035977892f * (float)ci);    // ln(1e4)/256
        float s1, c1, s2, c2;
        sincosf(fr, &s1, &c1);
        sincosf(2.f * fr, &s2, &c2);
        if (c < 256) {
            aq += wq;
            a0 += c2 * wk; a1 += c1 * wk; a2 += c1 * wk; a3 += c2 * wk;
        } else {
            a0 -= s2 * wk; a1 -= s1 * wk; a2 += s1 * wk; a3 += s2 * wk;
        }
    }
    for (int o = 16; o; o >>= 1) {
        aq += __shfl_xor_sync(0xffffffffu, aq, o);
        a0 += __shfl_xor_sync(0xffffffffu, a0, o);
        a1 += __shfl_xor_sync(0xffffffffu, a1, o);
        a2 += __shfl_xor_sync(0xffffffffu, a2, o);
        a3 += __shfl_xor_sync(0xffffffffu, a3, o);
    }
    if (lane == 0) {
        g_qb[j] = aq + b_q[j];
        float bk = b_k[j];
        g_kb[0 * 512 + j] = a0 + bk;
        g_kb[1 * 512 + j] = a1 + bk;
        g_kb[2 * 512 + j] = a2 + bk;
        g_kb[3 * 512 + j] = a3 + bk;
    }
}

// ---------------------------------------------------------------------------
// FP16 GEMM: C[M,N] = A[M,512] @ B[N,512]^T, fp32 accumulate.
// 128x128x32 CTA tile, 4-stage cp.async pipeline (single sync per K-iter),
// 8 warps (2x4), warp tile 64x32, mma.sync.m16n8k16 + ldmatrix.x4.
// Stage = As(128x20 u32) + Bs(128x20 u32) = 20480B; 4 stages = 81920B dynsmem.
// Post-loop the stage memory is reused for a coalescing epilogue tile.
// ---------------------------------------------------------------------------
__device__ __forceinline__ void cpa16(uint32_t dst, const void* src) {
    asm volatile("cp.async.cg.shared.global [%0], [%1], 16;\n" :: "r"(dst), "l"(src));
}
__device__ __forceinline__ void mma_f16(float* c, const uint32_t* a, const uint32_t* b) {
    asm volatile(
        "mma.sync.aligned.m16n8k16.row.col.f32.f16.f16.f32 "
        "{%0,%1,%2,%3}, {%4,%5,%6,%7}, {%8,%9}, {%0,%1,%2,%3};"
        : "+f"(c[0]), "+f"(c[1]), "+f"(c[2]), "+f"(c[3])
        : "r"(a[0]), "r"(a[1]), "r"(a[2]), "r"(a[3]), "r"(b[0]), "r"(b[1]));
}
__device__ __forceinline__ void ldsm4(uint32_t& r0, uint32_t& r1, uint32_t& r2,
                                      uint32_t& r3, uint32_t a) {
    asm volatile("ldmatrix.sync.aligned.m8n8.x4.shared.b16 {%0,%1,%2,%3}, [%4];"
                 : "=r"(r0), "=r"(r1), "=r"(r2), "=r"(r3) : "r"(a));
}

#define GEMM_DYNSMEM 81920

template <int MODE>
__global__ void __launch_bounds__(256) gemm_fp16(const float* __restrict__ xres,
                                                 float* __restrict__ out,
                                                 const float* __restrict__ b_proj) {
    constexpr int LDS_ = 20;                 // pitch in half2 units (80B/row)
    constexpr uint32_t STAGE = 128 * LDS_ * 4 * 2;   // 20480B (A+B)
    const __half* A = (MODE == 0) ? g_xn   : g_attn;
    const __half* B = (MODE == 0) ? g_wcat : g_wproj;

    extern __shared__ __align__(16) uint8_t dynsm[];
    uint32_t dsb = (uint32_t)__cvta_generic_to_shared(dynsm);

    int m0 = blockIdx.y * 128;
    int n0 = blockIdx.x * 128;
    int tid = threadIdx.x;
    int wid = tid >> 5, lane = tid & 31;
    int wm = (wid & 1) * 64, wn = (wid >> 1) * 32;
    int g = lane >> 2, tg = lane & 3;

    // ldmatrix lane address components
    int a_row = wm + (lane & 15);                       // + im*16
    int a_col = (lane >> 4) << 2;                       // 0 or 4 (uint32)
    int b_row = wn + ((lane >> 4) << 3) + (lane & 7);   // + 16*pair
    int b_col = ((lane >> 3) & 1) << 2;                 // 0 or 4

    int lrow = tid >> 2, lc = tid & 3;                  // cp.async mapping
    uint32_t soff0 = (uint32_t)((lrow * LDS_ + lc * 4) * 4);
    uint32_t soff1 = (uint32_t)(((lrow + 64) * LDS_ + lc * 4) * 4);

    auto load_tile = [&](int kt, int slot) {
        uint32_t base = dsb + (uint32_t)slot * STAGE;
        const __half* a = A + (size_t)(m0 + lrow) * 512 + kt * 32 + lc * 8;
        const __half* b = B + (size_t)(n0 + lrow) * 512 + kt * 32 + lc * 8;
        cpa16(base + soff0, a);
        cpa16(base + soff1, a + 64 * 512);
        cpa16(base + 10240u + soff0, b);
        cpa16(base + 10240u + soff1, b + 64 * 512);
        asm volatile("cp.async.commit_group;\n" ::);
    };

    float acc[4][4][4];
    #pragma unroll
    for (int i = 0; i < 4; i++)
        #pragma unroll
        for (int j = 0; j < 4; j++)
            #pragma unroll
            for (int r = 0; r < 4; r++) acc[i][j][r] = 0.f;

    load_tile(0, 0); load_tile(1, 1); load_tile(2, 2);

    for (int kt = 0; kt < 16; ++kt) {        // K = 512 / 32
        if (kt <= 13)      asm volatile("cp.async.wait_group 2;\n" ::);
        else if (kt == 14) asm volatile("cp.async.wait_group 1;\n" ::);
        else               asm volatile("cp.async.wait_group 0;\n" ::);
        __syncthreads();                     // stage kt visible; kt-1 consumed by all

        if (kt + 3 < 16) load_tile(kt + 3, (kt + 3) & 3);

        uint32_t abase = dsb + (uint32_t)(kt & 3) * STAGE;
        uint32_t bbase = abase + 10240u;
        #pragma unroll
        for (int kk = 0; kk < 2; ++kk) {     // two k16 steps per 32-half tile
            int kb = kk * 8;                 // half2 col base
            uint32_t af[4][4], bf[4][2];
            #pragma unroll
            for (int im = 0; im < 4; im++)
                ldsm4(af[im][0], af[im][1], af[im][2], af[im][3],
                      abase + (uint32_t)(((a_row + im * 16) * LDS_ + kb + a_col) * 4));
            #pragma unroll
            for (int p = 0; p < 2; p++)
                ldsm4(bf[2 * p][0], bf[2 * p][1], bf[2 * p + 1][0], bf[2 * p + 1][1],
                      bbase + (uint32_t)(((b_row + 16 * p) * LDS_ + kb + b_col) * 4));
            #pragma unroll
            for (int im = 0; im < 4; im++)
                #pragma unroll
                for (int in = 0; in < 4; in++)
                    mma_f16(acc[im][in], af[im], bf[in]);
        }
    }
    __syncthreads();                         // all compute done; reuse smem

    if (MODE == 0) {
        // re-tile to half2 smem [128 rows][64 half2], pitch 65 -> coalesced stores
        uint32_t* sep = (uint32_t*)dynsm;
        #pragma unroll
        for (int im = 0; im < 4; im++)
            #pragma unroll
            for (int in = 0; in < 4; in++) {
                int r = wm + im * 16 + g;
                int c2 = (wn >> 1) + in * 4 + tg;
                __half2 lo = __floats2half2_rn(acc[im][in][0], acc[im][in][1]);
                __half2 hi = __floats2half2_rn(acc[im][in][2], acc[im][in][3]);
                sep[r * 65 + c2]       = *(uint32_t*)&lo;
                sep[(r + 8) * 65 + c2] = *(uint32_t*)&hi;
            }
        __syncthreads();
        #pragma unroll
        for (int i = 0; i < 32; i++) {       // 8192 half2 / 256 threads
            int idx = tid + i * 256;
            int row = idx >> 6, c2 = idx & 63;
            *(__half2*)&g_qkv[(size_t)(m0 + row) * NQKV + n0 + 2 * c2] =
                *(__half2*)&sep[row * 65 + c2];
        }
    } else {
        // re-tile to fp32 smem [128 rows][128 cols], pitch 129 -> coalesced
        // out[t, c, hw] stores (128 consecutive hw per column)
        float* sep = (float*)dynsm;
        #pragma unroll
        for (int im = 0; im < 4; im++)
            #pragma unroll
            for (int in = 0; in < 4; in++) {
                int r = wm + im * 16 + g;
                int c = wn + in * 8 + tg * 2;
                sep[r * 129 + c]           = acc[im][in][0];
                sep[r * 129 + c + 1]       = acc[im][in][1];
                sep[(r + 8) * 129 + c]     = acc[im][in][2];
                sep[(r + 8) * 129 + c + 1] = acc[im][in][3];
            }
        __syncthreads();
        int tt = m0 >> 10, hwb = m0 & 1023;
        #pragma unroll
        for (int i = 0; i < 64; i++) {       // 16384 floats / 256 threads
            int idx = tid + i * 256;
            int c = idx >> 7, row = idx & 127;
            size_t oi = ((size_t)tt * C_DIM + n0 + c) * HW_DIM + hwb + row;
            out[oi] = sep[row * 129 + c] + b_proj[n0 + c] + xres[oi];
        }
    }
}

// ---------------------------------------------------------------------------
// Attention: one warp per token; fp16 raw Q/K/V; all biases folded here in
// fp32: score = (q+qb)·(k+kb);  out = sum_f p_f v_f + b_v (sum p = 1).
// ---------------------------------------------------------------------------
__global__ void __launch_bounds__(256) attn_kernel(const float* __restrict__ b_v) {
    int wid = threadIdx.x >> 5, lane = threadIdx.x & 31;
    int token = blockIdx.x * 8 + wid;
    int t = token >> 10, hw = token & 1023;
    const int offs[4] = {-2, -1, 1, 2};
    size_t kvbase[4];
    #pragma unroll
    for (int fi = 0; fi < 4; fi++) {
        int ts = t + offs[fi];
        ts = ts < 0 ? 0 : (ts > 15 ? 15 : ts);
        kvbase[fi] = (size_t)((ts << 10) | hw) * NQKV;
    }
    const __half2* Q2 = (const __half2*)(g_qkv + (size_t)token * NQKV);
    __half2* O2 = (__half2*)(g_attn + (size_t)token * C_DIM);

    #pragma unroll
    for (int h = 0; h < 8; ++h) {
        int cb2 = h * 32;                          // half2 index base
        float2 qb = ((const float2*)g_qb)[cb2 + lane];
        float2 q = __half22float2(Q2[cb2 + lane]);
        q.x += qb.x; q.y += qb.y;
        float s[4];
        #pragma unroll
        for (int fi = 0; fi < 4; fi++) {
            const __half2* K2 = (const __half2*)(g_qkv + kvbase[fi] + 512) + cb2;
            const float2* KB2 = (const float2*)(g_kb + fi * 512) + cb2;
            float2 k = __half22float2(K2[lane]);
            float2 kb = KB2[lane];
            float p = q.x * (k.x + kb.x) + q.y * (k.y + kb.y);
            for (int o = 16; o; o >>= 1) p += __shfl_xor_sync(0xffffffffu, p, o);
            s[fi] = p * 0.125f;                    // dh^-0.5, dh=64
        }
        float m = fmaxf(fmaxf(s[0], s[1]), fmaxf(s[2], s[3]));
        float e[4], sum = 0.f;
        #pragma unroll
        for (int fi = 0; fi < 4; fi++) { e[fi] = __expf(s[fi] - m); sum += e[fi]; }
        float inv = 1.f / sum;
        float ax = 0.f, ay = 0.f;
        #pragma unroll
        for (int fi = 0; fi < 4; fi++) {
            const __half2* V2 = (const __half2*)(g_qkv + kvbase[fi] + 1024) + cb2;
            float2 v = __half22float2(V2[lane]);
            float p = e[fi] * inv;
            ax += p * v.x;
            ay += p * v.y;
        }
        float2 bv = ((const float2*)b_v)[cb2 + lane];
        O2[cb2 + lane] = __floats2half2_rn(ax + bv.x, ay + bv.y);
    }
}

// ---------------------------------------------------------------------------
extern "C" void kernel_launch(void* const* d_in, const int* in_sizes, int n_in,
                              void* d_out, int out_size) {
    const float* x       = (const float*)d_in[0];
    const float* w_q     = (const float*)d_in[1];
    const float* b_q     = (const float*)d_in[2];
    const float* w_k     = (const float*)d_in[3];
    const float* b_k     = (const float*)d_in[4];
    const float* w_v     = (const float*)d_in[5];
    const float* b_v     = (const float*)d_in[6];
    const float* w_proj  = (const float*)d_in[7];
    const float* b_proj  = (const float*)d_in[8];
    const float* gn_s    = (const float*)d_in[9];
    const float* gn_b    = (const float*)d_in[10];
    float* out = (float*)d_out;

    // Unconditional every call: deterministic, not stream-ordered (capture-safe).
    cudaFuncSetAttribute(gemm_fp16<0>, cudaFuncAttributeMaxDynamicSharedMemorySize, GEMM_DYNSMEM);
    cudaFuncSetAttribute(gemm_fp16<1>, cudaFuncAttributeMaxDynamicSharedMemorySize, GEMM_DYNSMEM);

    gn_stats<<<512, 256>>>(x);
    gn_apply<<<dim3(32, 16, 16), dim3(32, 8)>>>(x, gn_s, gn_b);
    prep_bias<<<1088, 256>>>(w_q, w_k, w_v, w_proj, b_q, b_k);
    gemm_fp16<0><<<dim3(12, 128), 256, GEMM_DYNSMEM>>>(nullptr, nullptr, nullptr);
    attn_kernel<<<2048, 256>>>(b_v);
    gemm_fp16<1><<<dim3(4, 128), 256, GEMM_DYNSMEM>>>(x, out, b_proj);
}

// round 11
// speedup vs baseline: 5.3780x; 1.1040x over previous
#include <cuda_runtime.h>
#include <cuda_fp16.h>
#include <cstdint>

// ---------------------------------------------------------------------------
// TemporalAttention, B200 (compute_100 target -> legacy mma.sync path).
// R11: warp tile 64x64 (4 warps/CTA, 128 threads), CUTLASS-style ILP ratio.
// 128x128x32 CTA tile, 4-stage cp.async pipeline, coalesced smem epilogues.
// Order: gn_stats, gn_apply, prep_bias, gemm0, attn, gemm1
// ---------------------------------------------------------------------------

#define T_DIM   16
#define C_DIM   512
#define HW_DIM  1024
#define NTOK    16384
#define NQKV    1536
#define NGRP    32
#define GN_EPS  1e-5f

__device__ __half g_xn  [NTOK * C_DIM];
__device__ __half g_qkv [NTOK * NQKV];      // raw Q|K|V (biases applied in attn)
__device__ __half g_attn[NTOK * C_DIM];
__device__ __half g_wcat[NQKV * C_DIM];
__device__ __half g_wproj[C_DIM * C_DIM];
__device__ float  g_mu[512];
__device__ float  g_rs[512];
__device__ float  g_qb[C_DIM];              // b_q + t_mid @ Wq^T
__device__ float  g_kb[4 * C_DIM];          // b_k + t_rest[fi] @ Wk^T

// ---------------------------------------------------------------------------
__global__ void __launch_bounds__(256) gn_stats(const float* __restrict__ x) {
    int b = blockIdx.x;                       // t*32 + g
    const float4* base = (const float4*)(x + (size_t)b * 16384);
    float s = 0.f, s2 = 0.f;
    #pragma unroll
    for (int i = 0; i < 16; i++) {            // 16 * 256 * 4 = 16384 floats
        float4 v = base[threadIdx.x + i * 256];
        s  += v.x + v.y + v.z + v.w;
        s2 += v.x * v.x + v.y * v.y + v.z * v.z + v.w * v.w;
    }
    for (int o = 16; o; o >>= 1) {
        s  += __shfl_xor_sync(0xffffffffu, s,  o);
        s2 += __shfl_xor_sync(0xffffffffu, s2, o);
    }
    __shared__ float rs[8], rs2[8];
    int wid = threadIdx.x >> 5;
    if ((threadIdx.x & 31) == 0) { rs[wid] = s; rs2[wid] = s2; }
    __syncthreads();
    if (threadIdx.x == 0) {
        float a = 0.f, a2 = 0.f;
        #pragma unroll
        for (int i = 0; i < 8; i++) { a += rs[i]; a2 += rs2[i]; }
        float mu  = a  * (1.f / 16384.f);
        float var = a2 * (1.f / 16384.f) - mu * mu;
        g_mu[b] = mu;
        g_rs[b] = rsqrtf(var + GN_EPS);
    }
}

// ---------------------------------------------------------------------------
// GN apply + transpose [t,c,hw] -> [token, c], fp16 output
// ---------------------------------------------------------------------------
__global__ void __launch_bounds__(256) gn_apply(const float* __restrict__ x,
                                                const float* __restrict__ gs,
                                                const float* __restrict__ gb) {
    __shared__ float tile[32][33];
    int t   = blockIdx.z;
    int c0  = blockIdx.y * 32;
    int hw0 = blockIdx.x * 32;
    #pragma unroll
    for (int i = 0; i < 4; i++) {
        int c = c0 + threadIdx.y + i * 8;
        float v = x[((size_t)t * C_DIM + c) * HW_DIM + hw0 + threadIdx.x];
        int grp = c >> 4;
        v = (v - g_mu[t * NGRP + grp]) * g_rs[t * NGRP + grp] * gs[c] + gb[c];
        tile[threadIdx.y + i * 8][threadIdx.x] = v;
    }
    __syncthreads();
    #pragma unroll
    for (int i = 0; i < 4; i++) {
        int hw = hw0 + threadIdx.y + i * 8;
        g_xn[((size_t)t * HW_DIM + hw) * C_DIM + c0 + threadIdx.x] =
            __float2half_rn(tile[threadIdx.x][threadIdx.y + i * 8]);
    }
}

// ---------------------------------------------------------------------------
// prep_bias: blocks [0,1024) convert weights to fp16; blocks [1024,1088)
// compute qb/kb (one warp per output channel, coalesced + shfl reduce).
// ---------------------------------------------------------------------------
__global__ void __launch_bounds__(256) prep_bias(const float* __restrict__ w_q,
                                                 const float* __restrict__ w_k,
                                                 const float* __restrict__ w_v,
                                                 const float* __restrict__ w_proj,
                                                 const float* __restrict__ b_q,
                                                 const float* __restrict__ b_k) {
    if (blockIdx.x < 1024) {
        int i = blockIdx.x * 256 + threadIdx.x;
        g_wcat[i]          = __float2half_rn(w_q[i]);
        g_wcat[262144 + i] = __float2half_rn(w_k[i]);
        g_wcat[524288 + i] = __float2half_rn(w_v[i]);
        g_wproj[i]         = __float2half_rn(w_proj[i]);
        return;
    }
    int wid = threadIdx.x >> 5, lane = threadIdx.x & 31;
    int j = (blockIdx.x - 1024) * 8 + wid;        // 0..511
    float aq = 0.f, a0 = 0.f, a1 = 0.f, a2 = 0.f, a3 = 0.f;
    for (int c = lane; c < 512; c += 32) {
        float wq = w_q[j * 512 + c];
        float wk = w_k[j * 512 + c];
        int ci = (c < 256) ? c : c - 256;
        float fr = __expf(-0.035977892f * (float)ci);    // ln(1e4)/256
        float s1, c1, s2, c2;
        sincosf(fr, &s1, &c1);
        sincosf(2.f * fr, &s2, &c2);
        if (c < 256) {
            aq += wq;
            a0 += c2 * wk; a1 += c1 * wk; a2 += c1 * wk; a3 += c2 * wk;
        } else {
            a0 -= s2 * wk; a1 -= s1 * wk; a2 += s1 * wk; a3 += s2 * wk;
        }
    }
    for (int o = 16; o; o >>= 1) {
        aq += __shfl_xor_sync(0xffffffffu, aq, o);
        a0 += __shfl_xor_sync(0xffffffffu, a0, o);
        a1 += __shfl_xor_sync(0xffffffffu, a1, o);
        a2 += __shfl_xor_sync(0xffffffffu, a2, o);
        a3 += __shfl_xor_sync(0xffffffffu, a3, o);
    }
    if (lane == 0) {
        g_qb[j] = aq + b_q[j];
        float bk = b_k[j];
        g_kb[0 * 512 + j] = a0 + bk;
        g_kb[1 * 512 + j] = a1 + bk;
        g_kb[2 * 512 + j] = a2 + bk;
        g_kb[3 * 512 + j] = a3 + bk;
    }
}

// ---------------------------------------------------------------------------
// FP16 GEMM: C[M,N] = A[M,512] @ B[N,512]^T, fp32 accumulate.
// 128x128x32 CTA tile, 4 warps, warp tile 64x64 (2x2 warp grid),
// 4-stage cp.async pipeline (single sync per K-iter),
// mma.sync.m16n8k16 + ldmatrix.x4. Per k16 step: 8 LDSM feed 32 HMMA.
// Stage = 20480B; 4 stages = 81920B dynsmem, reused by epilogue re-tile.
// ---------------------------------------------------------------------------
__device__ __forceinline__ void cpa16(uint32_t dst, const void* src) {
    asm volatile("cp.async.cg.shared.global [%0], [%1], 16;\n" :: "r"(dst), "l"(src));
}
__device__ __forceinline__ void mma_f16(float* c, const uint32_t* a, const uint32_t* b) {
    asm volatile(
        "mma.sync.aligned.m16n8k16.row.col.f32.f16.f16.f32 "
        "{%0,%1,%2,%3}, {%4,%5,%6,%7}, {%8,%9}, {%0,%1,%2,%3};"
        : "+f"(c[0]), "+f"(c[1]), "+f"(c[2]), "+f"(c[3])
        : "r"(a[0]), "r"(a[1]), "r"(a[2]), "r"(a[3]), "r"(b[0]), "r"(b[1]));
}
__device__ __forceinline__ void ldsm4(uint32_t& r0, uint32_t& r1, uint32_t& r2,
                                      uint32_t& r3, uint32_t a) {
    asm volatile("ldmatrix.sync.aligned.m8n8.x4.shared.b16 {%0,%1,%2,%3}, [%4];"
                 : "=r"(r0), "=r"(r1), "=r"(r2), "=r"(r3) : "r"(a));
}

#define GEMM_DYNSMEM 81920

template <int MODE>
__global__ void __launch_bounds__(128, 2) gemm_fp16(const float* __restrict__ xres,
                                                    float* __restrict__ out,
                                                    const float* __restrict__ b_proj) {
    constexpr int LDS_ = 20;                 // pitch in half2 units (80B/row)
    constexpr uint32_t STAGE = 128 * LDS_ * 4 * 2;   // 20480B (A+B)
    const __half* A = (MODE == 0) ? g_xn   : g_attn;
    const __half* B = (MODE == 0) ? g_wcat : g_wproj;

    extern __shared__ __align__(16) uint8_t dynsm[];
    uint32_t dsb = (uint32_t)__cvta_generic_to_shared(dynsm);

    int m0 = blockIdx.y * 128;
    int n0 = blockIdx.x * 128;
    int tid = threadIdx.x;
    int wid = tid >> 5, lane = tid & 31;
    int wm = (wid & 1) * 64, wn = (wid >> 1) * 64;   // 2x2 warp grid
    int g = lane >> 2, tg = lane & 3;

    // ldmatrix lane address components
    int a_row = wm + (lane & 15);                       // + im*16
    int a_col = (lane >> 4) << 2;                       // 0 or 4 (uint32)
    int b_row = wn + ((lane >> 4) << 3) + (lane & 7);   // + 16*pair (4 pairs)
    int b_col = ((lane >> 3) & 1) << 2;                 // 0 or 4

    auto load_tile = [&](int kt, int slot) {
        uint32_t base = dsb + (uint32_t)slot * STAGE;
        #pragma unroll
        for (int j = 0; j < 4; j++) {
            int id = tid + j * 128;
            int row = id >> 2, c = id & 3;
            uint32_t soff = (uint32_t)((row * LDS_ + c * 4) * 4);
            cpa16(base + soff, A + (size_t)(m0 + row) * 512 + kt * 32 + c * 8);
            cpa16(base + 10240u + soff, B + (size_t)(n0 + row) * 512 + kt * 32 + c * 8);
        }
        asm volatile("cp.async.commit_group;\n" ::);
    };

    float acc[4][8][4];
    #pragma unroll
    for (int i = 0; i < 4; i++)
        #pragma unroll
        for (int j = 0; j < 8; j++)
            #pragma unroll
            for (int r = 0; r < 4; r++) acc[i][j][r] = 0.f;

    load_tile(0, 0); load_tile(1, 1); load_tile(2, 2);

    for (int kt = 0; kt < 16; ++kt) {        // K = 512 / 32
        if (kt <= 13)      asm volatile("cp.async.wait_group 2;\n" ::);
        else if (kt == 14) asm volatile("cp.async.wait_group 1;\n" ::);
        else               asm volatile("cp.async.wait_group 0;\n" ::);
        __syncthreads();                     // stage kt visible; kt-1 consumed by all

        if (kt + 3 < 16) load_tile(kt + 3, (kt + 3) & 3);

        uint32_t abase = dsb + (uint32_t)(kt & 3) * STAGE;
        uint32_t bbase = abase + 10240u;
        #pragma unroll
        for (int kk = 0; kk < 2; ++kk) {     // two k16 steps per 32-half tile
            int kb = kk * 8;                 // half2 col base
            uint32_t af[4][4], bf[8][2];
            #pragma unroll
            for (int im = 0; im < 4; im++)
                ldsm4(af[im][0], af[im][1], af[im][2], af[im][3],
                      abase + (uint32_t)(((a_row + im * 16) * LDS_ + kb + a_col) * 4));
            #pragma unroll
            for (int p = 0; p < 4; p++)
                ldsm4(bf[2 * p][0], bf[2 * p][1], bf[2 * p + 1][0], bf[2 * p + 1][1],
                      bbase + (uint32_t)(((b_row + 16 * p) * LDS_ + kb + b_col) * 4));
            #pragma unroll
            for (int im = 0; im < 4; im++)
                #pragma unroll
                for (int in = 0; in < 8; in++)
                    mma_f16(acc[im][in], af[im], bf[in]);
        }
    }
    __syncthreads();                         // all compute done; reuse smem

    if (MODE == 0) {
        // re-tile to half2 smem [128 rows][64 half2], pitch 65 -> coalesced stores
        uint32_t* sep = (uint32_t*)dynsm;
        #pragma unroll
        for (int im = 0; im < 4; im++)
            #pragma unroll
            for (int in = 0; in < 8; in++) {
                int r = wm + im * 16 + g;
                int c2 = (wn >> 1) + in * 4 + tg;
                __half2 lo = __floats2half2_rn(acc[im][in][0], acc[im][in][1]);
                __half2 hi = __floats2half2_rn(acc[im][in][2], acc[im][in][3]);
                sep[r * 65 + c2]       = *(uint32_t*)&lo;
                sep[(r + 8) * 65 + c2] = *(uint32_t*)&hi;
            }
        __syncthreads();
        #pragma unroll
        for (int i = 0; i < 64; i++) {       // 8192 half2 / 128 threads
            int idx = tid + i * 128;
            int row = idx >> 6, c2 = idx & 63;
            *(__half2*)&g_qkv[(size_t)(m0 + row) * NQKV + n0 + 2 * c2] =
                *(__half2*)&sep[row * 65 + c2];
        }
    } else {
        // re-tile to fp32 smem [128 rows][128 cols], pitch 129 -> coalesced
        // out[t, c, hw] stores (128 consecutive hw per column)
        float* sep = (float*)dynsm;
        #pragma unroll
        for (int im = 0; im < 4; im++)
            #pragma unroll
            for (int in = 0; in < 8; in++) {
                int r = wm + im * 16 + g;
                int c = wn + in * 8 + tg * 2;
                sep[r * 129 + c]           = acc[im][in][0];
                sep[r * 129 + c + 1]       = acc[im][in][1];
                sep[(r + 8) * 129 + c]     = acc[im][in][2];
                sep[(r + 8) * 129 + c + 1] = acc[im][in][3];
            }
        __syncthreads();
        int tt = m0 >> 10, hwb = m0 & 1023;
        #pragma unroll
        for (int i = 0; i < 128; i++) {      // 16384 floats / 128 threads
            int idx = tid + i * 128;
            int c = idx >> 7, row = idx & 127;
            size_t oi = ((size_t)tt * C_DIM + n0 + c) * HW_DIM + hwb + row;
            out[oi] = sep[row * 129 + c] + b_proj[n0 + c] + xres[oi];
        }
    }
}

// ---------------------------------------------------------------------------
// Attention: one warp per token; fp16 raw Q/K/V; all biases folded here in
// fp32: score = (q+qb)·(k+kb);  out = sum_f p_f v_f + b_v (sum p = 1).
// ---------------------------------------------------------------------------
__global__ void __launch_bounds__(256) attn_kernel(const float* __restrict__ b_v) {
    int wid = threadIdx.x >> 5, lane = threadIdx.x & 31;
    int token = blockIdx.x * 8 + wid;
    int t = token >> 10, hw = token & 1023;
    const int offs[4] = {-2, -1, 1, 2};
    size_t kvbase[4];
    #pragma unroll
    for (int fi = 0; fi < 4; fi++) {
        int ts = t + offs[fi];
        ts = ts < 0 ? 0 : (ts > 15 ? 15 : ts);
        kvbase[fi] = (size_t)((ts << 10) | hw) * NQKV;
    }
    const __half2* Q2 = (const __half2*)(g_qkv + (size_t)token * NQKV);
    __half2* O2 = (__half2*)(g_attn + (size_t)token * C_DIM);

    #pragma unroll
    for (int h = 0; h < 8; ++h) {
        int cb2 = h * 32;                          // half2 index base
        float2 qb = ((const float2*)g_qb)[cb2 + lane];
        float2 q = __half22float2(Q2[cb2 + lane]);
        q.x += qb.x; q.y += qb.y;
        float s[4];
        #pragma unroll
        for (int fi = 0; fi < 4; fi++) {
            const __half2* K2 = (const __half2*)(g_qkv + kvbase[fi] + 512) + cb2;
            const float2* KB2 = (const float2*)(g_kb + fi * 512) + cb2;
            float2 k = __half22float2(K2[lane]);
            float2 kb = KB2[lane];
            float p = q.x * (k.x + kb.x) + q.y * (k.y + kb.y);
            for (int o = 16; o; o >>= 1) p += __shfl_xor_sync(0xffffffffu, p, o);
            s[fi] = p * 0.125f;                    // dh^-0.5, dh=64
        }
        float m = fmaxf(fmaxf(s[0], s[1]), fmaxf(s[2], s[3]));
        float e[4], sum = 0.f;
        #pragma unroll
        for (int fi = 0; fi < 4; fi++) { e[fi] = __expf(s[fi] - m); sum += e[fi]; }
        float inv = 1.f / sum;
        float ax = 0.f, ay = 0.f;
        #pragma unroll
        for (int fi = 0; fi < 4; fi++) {
            const __half2* V2 = (const __half2*)(g_qkv + kvbase[fi] + 1024) + cb2;
            float2 v = __half22float2(V2[lane]);
            float p = e[fi] * inv;
            ax += p * v.x;
            ay += p * v.y;
        }
        float2 bv = ((const float2*)b_v)[cb2 + lane];
        O2[cb2 + lane] = __floats2half2_rn(ax + bv.x, ay + bv.y);
    }
}

// ---------------------------------------------------------------------------
extern "C" void kernel_launch(void* const* d_in, const int* in_sizes, int n_in,
                              void* d_out, int out_size) {
    const float* x       = (const float*)d_in[0];
    const float* w_q     = (const float*)d_in[1];
    const float* b_q     = (const float*)d_in[2];
    const float* w_k     = (const float*)d_in[3];
    const float* b_k     = (const float*)d_in[4];
    const float* w_v     = (const float*)d_in[5];
    const float* b_v     = (const float*)d_in[6];
    const float* w_proj  = (const float*)d_in[7];
    const float* b_proj  = (const float*)d_in[8];
    const float* gn_s    = (const float*)d_in[9];
    const float* gn_b    = (const float*)d_in[10];
    float* out = (float*)d_out;

    // Unconditional every call: deterministic, not stream-ordered (capture-safe).
    cudaFuncSetAttribute(gemm_fp16<0>, cudaFuncAttributeMaxDynamicSharedMemorySize, GEMM_DYNSMEM);
    cudaFuncSetAttribute(gemm_fp16<1>, cudaFuncAttributeMaxDynamicSharedMemorySize, GEMM_DYNSMEM);

    gn_stats<<<512, 256>>>(x);
    gn_apply<<<dim3(32, 16, 16), dim3(32, 8)>>>(x, gn_s, gn_b);
    prep_bias<<<1088, 256>>>(w_q, w_k, w_v, w_proj, b_q, b_k);
    gemm_fp16<0><<<dim3(12, 128), 128, GEMM_DYNSMEM>>>(nullptr, nullptr, nullptr);
    attn_kernel<<<2048, 256>>>(b_v);
    gemm_fp16<1><<<dim3(4, 128), 128, GEMM_DYNSMEM>>>(x, out, b_proj);
}